// round 2
// baseline (speedup 1.0000x reference)
#include <cuda_runtime.h>
#include <math.h>
#include <float.h>

#define BATCH 8
#define NPT   2048
#define M1C   1024
#define M2C   256
#define KNB   64
#define CURVK 10

// ---- scratch (device globals; no allocation) ----
__device__ float g_curv [BATCH*NPT];
__device__ int   g_fps1 [BATCH*M1C];
__device__ int   g_fps2 [BATCH*M2C];
__device__ float g_pos1 [BATCH*M1C*3];
__device__ float g_curv1[BATCH*M1C];
__device__ float g_pos2 [BATCH*M2C*3];
__device__ int   g_nidx1[BATCH*M1C*KNB];
__device__ int   g_cnt1 [BATCH*M1C];
__device__ int   g_nidx2[BATCH*M2C*KNB];
__device__ int   g_cnt2 [BATCH*M2C];
__device__ float g_x1   [BATCH*M1C*128];
__device__ float g_x2   [BATCH*M2C*256];
__device__ float g_gfeat[BATCH*1024];
__device__ float g_featF[BATCH*M2C*KNB*131];          // 17.2M floats (max feats)
__device__ float g_bufA [(size_t)BATCH*M1C*KNB*64];   // 33.55M floats
__device__ float g_bufB [(size_t)BATCH*M1C*KNB*64];

// ---- curvature: 10-NN covariance eigen ratio ----
__global__ void curvature_kernel(const float* __restrict__ pos, float* __restrict__ curv)
{
    __shared__ float px[NPT], py[NPT], pz[NPT], nr[NPT];
    const int b = blockIdx.x / (NPT/128);
    const int tid = threadIdx.x;
    const float* cp = pos + (size_t)b * NPT * 3;
    for (int i = tid; i < NPT; i += 128) {
        float x = cp[3*i], y = cp[3*i+1], z = cp[3*i+2];
        px[i]=x; py[i]=y; pz[i]=z; nr[i]=x*x+y*y+z*z;
    }
    __syncthreads();
    const int i = (blockIdx.x % (NPT/128)) * 128 + tid;
    const float qx=px[i], qy=py[i], qz=pz[i], nq=nr[i];

    float td[CURVK]; int ti[CURVK];
#pragma unroll
    for (int s = 0; s < CURVK; ++s) { td[s]=3.4e38f; ti[s]=0; }
    for (int j = 0; j < NPT; ++j) {
        float d2 = nq + nr[j] - 2.0f*(qx*px[j]+qy*py[j]+qz*pz[j]);
        if (d2 < td[CURVK-1]) {
            float cd=d2; int ci=j;
#pragma unroll
            for (int s = 0; s < CURVK; ++s)
                if (cd < td[s]) { float t=td[s]; td[s]=cd; cd=t; int u=ti[s]; ti[s]=ci; ci=u; }
        }
    }
    float mx=0,my=0,mz=0;
#pragma unroll
    for (int s = 0; s < CURVK; ++s) { mx+=px[ti[s]]; my+=py[ti[s]]; mz+=pz[ti[s]]; }
    mx/=CURVK; my/=CURVK; mz/=CURVK;
    double cxx=0,cxy=0,cxz=0,cyy=0,cyz=0,czz=0;
#pragma unroll
    for (int s = 0; s < CURVK; ++s) {
        float ax=px[ti[s]]-mx, ay=py[ti[s]]-my, az=pz[ti[s]]-mz;
        cxx+=(double)ax*ax; cxy+=(double)ax*ay; cxz+=(double)ax*az;
        cyy+=(double)ay*ay; cyz+=(double)ay*az; czz+=(double)az*az;
    }
    cxx/=CURVK; cxy/=CURVK; cxz/=CURVK; cyy/=CURVK; cyz/=CURVK; czz/=CURVK;
    double tr=cxx+cyy+czz;
    double p1=cxy*cxy+cxz*cxz+cyz*cyz;
    double q=tr/3.0;
    double p2=(cxx-q)*(cxx-q)+(cyy-q)*(cyy-q)+(czz-q)*(czz-q)+2.0*p1;
    double lmin;
    if (p2 < 1e-32) lmin = q;
    else {
        double p=sqrt(p2/6.0);
        double b00=(cxx-q)/p,b11=(cyy-q)/p,b22=(czz-q)/p,b01=cxy/p,b02=cxz/p,b12=cyz/p;
        double detB=b00*(b11*b22-b12*b12)-b01*(b01*b22-b12*b02)+b02*(b01*b12-b11*b02);
        double r=fmin(1.0,fmax(-1.0,detB*0.5));
        lmin=q+2.0*p*cos(acos(r)/3.0 + 2.0943951023931953);
    }
    curv[b*NPT+i]=(float)(lmin/(tr+1e-8));
}

// ---- weighted farthest point sampling ----
template<int NPTS,int MOUT>
__global__ void __launch_bounds__(1024) fps_kernel(const float* __restrict__ pos,
                                                   const float* __restrict__ curv,
                                                   int* __restrict__ out_idx)
{
    __shared__ float px[NPTS],py[NPTS],pz[NPTS],ww[NPTS],md[NPTS];
    __shared__ float rv[32]; __shared__ int ri[32]; __shared__ int sbest;
    const int b=blockIdx.x, tid=threadIdx.x;
    const float* cp = pos + (size_t)b*NPTS*3;
    for (int i = tid; i < NPTS; i += 1024) {
        px[i]=cp[3*i]; py[i]=cp[3*i+1]; pz[i]=cp[3*i+2];
        ww[i]=1.0f+10.0f*curv[b*NPTS+i];
    }
    __syncthreads();
    { float bx=px[0],by=py[0],bz=pz[0];
      for (int i = tid; i < NPTS; i += 1024) {
          float dx=px[i]-bx,dy=py[i]-by,dz=pz[i]-bz; md[i]=dx*dx+dy*dy+dz*dz; } }
    if (tid==0) out_idx[b*MOUT]=0;
    for (int m = 1; m < MOUT; ++m) {
        float bv=-1.0f; int bi=0;
#pragma unroll
        for (int e = 0; e < NPTS/1024; ++e) {
            int i = tid + e*1024;
            float v = md[i]*ww[i];
            if (v>bv || (v==bv && i<bi)) { bv=v; bi=i; }
        }
#pragma unroll
        for (int off = 16; off; off >>= 1) {
            float ov=__shfl_down_sync(0xffffffffu,bv,off);
            int oi=__shfl_down_sync(0xffffffffu,bi,off);
            if (ov>bv || (ov==bv && oi<bi)) { bv=ov; bi=oi; }
        }
        if ((tid&31)==0) { rv[tid>>5]=bv; ri[tid>>5]=bi; }
        __syncthreads();
        if (tid < 32) {
            bv=rv[tid]; bi=ri[tid];
#pragma unroll
            for (int off = 16; off; off >>= 1) {
                float ov=__shfl_down_sync(0xffffffffu,bv,off);
                int oi=__shfl_down_sync(0xffffffffu,bi,off);
                if (ov>bv || (ov==bv && oi<bi)) { bv=ov; bi=oi; }
            }
            if (tid==0) { sbest=bi; out_idx[b*MOUT+m]=bi; }
        }
        __syncthreads();
        const int s=sbest; const float sx=px[s],sy=py[s],sz=pz[s];
#pragma unroll
        for (int e = 0; e < NPTS/1024; ++e) {
            int i = tid + e*1024;
            float dx=px[i]-sx,dy=py[i]-sy,dz=pz[i]-sz;
            md[i]=fminf(md[i], dx*dx+dy*dy+dz*dz);
        }
        __syncthreads();
    }
}

__global__ void gather_kernel(const float* __restrict__ pos, const float* __restrict__ curv,
                              const int* __restrict__ idx, float* __restrict__ opos,
                              float* __restrict__ ocurv, int npts, int mout, int total)
{
    int t = blockIdx.x*256 + threadIdx.x;
    if (t >= total) return;
    int b = t / mout, i = idx[t], src = b*npts + i;
    opos[3*t]=pos[3*src]; opos[3*t+1]=pos[3*src+1]; opos[3*t+2]=pos[3*src+2];
    if (ocurv) ocurv[t]=curv[src];
}

// ---- radius grouping: up to KNB nearest within r (warp per centroid) ----
template<int NPTS,int CAP>
__global__ void group_kernel(const float* __restrict__ pts, const float* __restrict__ cents,
                             int* __restrict__ nidx, int* __restrict__ cnt_out,
                             int MC, float r2)
{
    __shared__ float px[NPTS],py[NPTS],pz[NPTS],nr[NPTS];
    __shared__ unsigned long long cand[2][CAP];
    const int b=blockIdx.y, tid=threadIdx.x;
    const float* cp = pts + (size_t)b*NPTS*3;
    for (int i = tid; i < NPTS; i += 64) {
        float x=cp[3*i],y=cp[3*i+1],z=cp[3*i+2];
        px[i]=x; py[i]=y; pz[i]=z; nr[i]=x*x+y*y+z*z;
    }
    __syncthreads();
    const int w=tid>>5, lane=tid&31;
    const int c=blockIdx.x*2+w, cg=b*MC+c;
    const float cx=cents[3*cg],cy=cents[3*cg+1],cz=cents[3*cg+2];
    const float nc=cx*cx+cy*cy+cz*cz;
    int cnt=0;
    for (int j0 = 0; j0 < NPTS; j0 += 32) {
        int j=j0+lane;
        float d2 = nc + nr[j] - 2.0f*(cx*px[j]+cy*py[j]+cz*pz[j]);
        bool in = (d2 <= r2);
        unsigned mask = __ballot_sync(0xffffffffu, in);
        if (in) {
            int p = cnt + __popc(mask & ((1u<<lane)-1u));
            if (p < CAP) {
                unsigned ub=__float_as_uint(d2);
                ub = (ub&0x80000000u) ? ~ub : (ub|0x80000000u);
                cand[w][p] = ((unsigned long long)ub<<32) | (unsigned)j;
            }
        }
        cnt += __popc(mask);
    }
    if (cnt > CAP) cnt = CAP;
    for (int i = cnt+lane; i < CAP; i += 32) cand[w][i]=0xFFFFFFFFFFFFFFFFull;
    __syncwarp();
    for (int k = 2; k <= CAP; k <<= 1)
        for (int j = k>>1; j > 0; j >>= 1) {
            for (int i = lane; i < CAP; i += 32) {
                int ixj = i^j;
                if (ixj > i) {
                    unsigned long long a=cand[w][i], bb=cand[w][ixj];
                    if ((a>bb) == ((i&k)==0)) { cand[w][i]=bb; cand[w][ixj]=a; }
                }
            }
            __syncwarp();
        }
    int nv = cnt < KNB ? cnt : KNB;
    int fb = (nv>0) ? (int)(cand[w][0]&0xffffffffu) : 0;
    for (int i = lane; i < KNB; i += 32)
        nidx[(size_t)cg*KNB+i] = (i<nv) ? (int)(cand[w][i]&0xffffffffu) : fb;
    if (lane==0) cnt_out[cg]=nv;
}

// ---- feature builders ----
__global__ void feats1_kernel(const float* __restrict__ pos, const float* __restrict__ pos1,
                              const int* __restrict__ nidx, float* __restrict__ f)
{
    int row = blockIdx.x*128 + threadIdx.x;     // B*M1*K rows
    int c = row/KNB, b = c/M1C, src = b*NPT + nidx[row];
    f[3*row]  =pos[3*src]  -pos1[3*c];
    f[3*row+1]=pos[3*src+1]-pos1[3*c+1];
    f[3*row+2]=pos[3*src+2]-pos1[3*c+2];
}
__global__ void feats2_kernel(const float* __restrict__ x1, const float* __restrict__ pos1,
                              const float* __restrict__ pos2, const int* __restrict__ nidx,
                              float* __restrict__ feats)
{
    int row = blockIdx.x*4 + (threadIdx.x>>5), lane = threadIdx.x&31;
    int c = row/KNB, b = c/M2C, p = nidx[row];
    const float* xs = x1 + (size_t)(b*M1C+p)*128;
    float* f = feats + (size_t)row*131;
    for (int i = lane; i < 128; i += 32) f[i]=xs[i];
    if (lane < 3) f[128+lane]=pos1[(b*M1C+p)*3+lane]-pos2[c*3+lane];
}
__global__ void feats3_kernel(const float* __restrict__ x2, const float* __restrict__ pos2,
                              float* __restrict__ feats)
{
    int row = blockIdx.x*4 + (threadIdx.x>>5), lane = threadIdx.x&31;
    const float* xs = x2 + (size_t)row*256;
    float* f = feats + (size_t)row*259;
    for (int i = lane; i < 256; i += 32) f[i]=xs[i];
    if (lane < 3) f[256+lane]=pos2[row*3+lane];
}

// ---- fp32 GEMM: C = act(A[M,Kc] @ W[Kc,N] + b), 64x64 tile ----
__global__ void __launch_bounds__(128) gemm_kernel(
    const float* __restrict__ A, const float* __restrict__ W,
    const float* __restrict__ bias, float* __restrict__ C, int N, int Kc, int relu)
{
    __shared__ float As[16*64], Ws[16*64];
    const int bn=blockIdx.x*64, bm=blockIdx.y*64, tid=threadIdx.x;
    const int tx=tid&15, ty=tid>>4;
    float acc[4][8];
#pragma unroll
    for (int i=0;i<4;++i)
#pragma unroll
        for (int j=0;j<8;++j) acc[i][j]=0.f;
    const int nkt=(Kc+15)>>4;
    for (int kt = 0; kt < nkt; ++kt) {
        const int k0=kt<<4;
#pragma unroll
        for (int r = 0; r < 8; ++r) {
            int e=tid+r*128;
            int k=e&15, row=e>>4;
            As[k*64+row] = (k0+k<Kc) ? A[(size_t)(bm+row)*Kc+k0+k] : 0.f;
            int n=e&63, kw=e>>6;
            Ws[kw*64+n] = (k0+kw<Kc) ? W[(size_t)(k0+kw)*N+bn+n] : 0.f;
        }
        __syncthreads();
#pragma unroll
        for (int k = 0; k < 16; ++k) {
            float4 a4=*(const float4*)&As[k*64+tx*4];
            float4 w0=*(const float4*)&Ws[k*64+ty*8];
            float4 w1=*(const float4*)&Ws[k*64+ty*8+4];
            float av[4]={a4.x,a4.y,a4.z,a4.w};
            float wv[8]={w0.x,w0.y,w0.z,w0.w,w1.x,w1.y,w1.z,w1.w};
#pragma unroll
            for (int i=0;i<4;++i)
#pragma unroll
                for (int j=0;j<8;++j) acc[i][j]+=av[i]*wv[j];
        }
        __syncthreads();
    }
#pragma unroll
    for (int i = 0; i < 4; ++i) {
        float* cp = C + (size_t)(bm+tx*4+i)*N + bn + ty*8;
#pragma unroll
        for (int j = 0; j < 8; ++j) {
            float v = acc[i][j] + bias[bn+ty*8+j];
            cp[j] = relu ? fmaxf(v,0.f) : v;
        }
    }
}

// ---- GEMM fused with masked max-pool over 64-row groups ----
__global__ void __launch_bounds__(128) gemm_maxpool_kernel(
    const float* __restrict__ A, const float* __restrict__ W,
    const float* __restrict__ bias, float* __restrict__ out,
    const int* __restrict__ cnt, int N, int Kc)
{
    __shared__ float As[16*64], Ws[16*64], red[16*64];
    const int g=blockIdx.y, bn=blockIdx.x*64, tid=threadIdx.x;
    const int tx=tid&15, ty=tid>>4;
    const size_t ab=(size_t)g*64*Kc;
    float acc[4][8];
#pragma unroll
    for (int i=0;i<4;++i)
#pragma unroll
        for (int j=0;j<8;++j) acc[i][j]=0.f;
    const int nkt=(Kc+15)>>4;
    for (int kt = 0; kt < nkt; ++kt) {
        const int k0=kt<<4;
#pragma unroll
        for (int r = 0; r < 8; ++r) {
            int e=tid+r*128;
            int k=e&15, row=e>>4;
            As[k*64+row] = (k0+k<Kc) ? A[ab+(size_t)row*Kc+k0+k] : 0.f;
            int n=e&63, kw=e>>6;
            Ws[kw*64+n] = (k0+kw<Kc) ? W[(size_t)(k0+kw)*N+bn+n] : 0.f;
        }
        __syncthreads();
#pragma unroll
        for (int k = 0; k < 16; ++k) {
            float4 a4=*(const float4*)&As[k*64+tx*4];
            float4 w0=*(const float4*)&Ws[k*64+ty*8];
            float4 w1=*(const float4*)&Ws[k*64+ty*8+4];
            float av[4]={a4.x,a4.y,a4.z,a4.w};
            float wv[8]={w0.x,w0.y,w0.z,w0.w,w1.x,w1.y,w1.z,w1.w};
#pragma unroll
            for (int i=0;i<4;++i)
#pragma unroll
                for (int j=0;j<8;++j) acc[i][j]+=av[i]*wv[j];
        }
        __syncthreads();
    }
    const int cv = cnt[g];
    float pm[8];
#pragma unroll
    for (int j=0;j<8;++j) pm[j]=-FLT_MAX;
#pragma unroll
    for (int i = 0; i < 4; ++i)
        if (tx*4+i < cv)
#pragma unroll
            for (int j=0;j<8;++j) pm[j]=fmaxf(pm[j], acc[i][j]+bias[bn+ty*8+j]);
#pragma unroll
    for (int j=0;j<8;++j) red[tx*64+ty*8+j]=pm[j];
    __syncthreads();
    if (tid < 64) {
        float m = red[tid];
        for (int t = 1; t < 16; ++t) m = fmaxf(m, red[t*64+tid]);
        out[(size_t)g*N + bn + tid] = (cv==0) ? 0.f : m;
    }
}

// ---- global max pool over M2 rows ----
__global__ void pool256_kernel(const float* __restrict__ g, float* __restrict__ gfeat)
{
    int b = blockIdx.y, f = blockIdx.x*256 + threadIdx.x;
    float m = -FLT_MAX;
    for (int r = 0; r < M2C; ++r)
        m = fmaxf(m, g[(size_t)(b*M2C+r)*1024 + f]);
    gfeat[b*1024+f]=m;
}

// ---- head MLP + log_softmax ----
__global__ void head_kernel(const float* __restrict__ gfeat,
                            const float* __restrict__ Wh1, const float* __restrict__ bh1,
                            const float* __restrict__ Wh2, const float* __restrict__ bh2,
                            const float* __restrict__ Wh3, const float* __restrict__ bh3,
                            float* __restrict__ out)
{
    __shared__ float gf[1024], h1[512], h2[256], lg[10];
    const int b=blockIdx.x, tid=threadIdx.x;
    for (int i = tid; i < 1024; i += 256) gf[i]=gfeat[b*1024+i];
    __syncthreads();
    for (int n = tid; n < 512; n += 256) {
        float s = bh1[n];
        for (int k = 0; k < 1024; ++k) s += gf[k]*Wh1[(size_t)k*512+n];
        h1[n]=fmaxf(s,0.f);
    }
    __syncthreads();
    { float s = bh2[tid];
      for (int k = 0; k < 512; ++k) s += h1[k]*Wh2[(size_t)k*256+tid];
      h2[tid]=fmaxf(s,0.f); }
    __syncthreads();
    if (tid < 10) {
        float s = bh3[tid];
        for (int k = 0; k < 256; ++k) s += h2[k]*Wh3[k*10+tid];
        lg[tid]=s;
    }
    __syncthreads();
    if (tid == 0) {
        float m=lg[0];
        for (int j=1;j<10;++j) m=fmaxf(m,lg[j]);
        float se=0.f;
        for (int j=0;j<10;++j) se+=expf(lg[j]-m);
        float l=logf(se);
        for (int j=0;j<10;++j) out[b*10+j]=lg[j]-m-l;
    }
}

extern "C" void kernel_launch(void* const* d_in, const int* in_sizes, int n_in,
                              void* d_out, int out_size)
{
    const float* pos=(const float*)d_in[0];
    const float *W1a=(const float*)d_in[1],  *b1a=(const float*)d_in[2];
    const float *W1b=(const float*)d_in[3],  *b1b=(const float*)d_in[4];
    const float *W1c=(const float*)d_in[5],  *b1c=(const float*)d_in[6];
    const float *W2a=(const float*)d_in[7],  *b2a=(const float*)d_in[8];
    const float *W2b=(const float*)d_in[9],  *b2b=(const float*)d_in[10];
    const float *W2c=(const float*)d_in[11], *b2c=(const float*)d_in[12];
    const float *W3a=(const float*)d_in[13], *b3a=(const float*)d_in[14];
    const float *W3b=(const float*)d_in[15], *b3b=(const float*)d_in[16];
    const float *W3c=(const float*)d_in[17], *b3c=(const float*)d_in[18];
    const float *Wh1=(const float*)d_in[19], *bh1=(const float*)d_in[20];
    const float *Wh2=(const float*)d_in[21], *bh2=(const float*)d_in[22];
    const float *Wh3=(const float*)d_in[23], *bh3=(const float*)d_in[24];

    float *curv,*pos1,*curv1,*pos2,*x1,*x2,*gfeat,*fF,*bA,*bB;
    int *fps1,*fps2,*nidx1,*cnt1,*nidx2,*cnt2;
    cudaGetSymbolAddress((void**)&curv, g_curv);
    cudaGetSymbolAddress((void**)&fps1, g_fps1);
    cudaGetSymbolAddress((void**)&fps2, g_fps2);
    cudaGetSymbolAddress((void**)&pos1, g_pos1);
    cudaGetSymbolAddress((void**)&curv1,g_curv1);
    cudaGetSymbolAddress((void**)&pos2, g_pos2);
    cudaGetSymbolAddress((void**)&nidx1,g_nidx1);
    cudaGetSymbolAddress((void**)&cnt1, g_cnt1);
    cudaGetSymbolAddress((void**)&nidx2,g_nidx2);
    cudaGetSymbolAddress((void**)&cnt2, g_cnt2);
    cudaGetSymbolAddress((void**)&x1,   g_x1);
    cudaGetSymbolAddress((void**)&x2,   g_x2);
    cudaGetSymbolAddress((void**)&gfeat,g_gfeat);
    cudaGetSymbolAddress((void**)&fF,   g_featF);
    cudaGetSymbolAddress((void**)&bA,   g_bufA);
    cudaGetSymbolAddress((void**)&bB,   g_bufB);

    // curvature + FPS level 1
    curvature_kernel<<<BATCH*(NPT/128), 128>>>(pos, curv);
    fps_kernel<NPT,M1C><<<BATCH, 1024>>>(pos, curv, fps1);
    gather_kernel<<<(BATCH*M1C+255)/256, 256>>>(pos, curv, fps1, pos1, curv1, NPT, M1C, BATCH*M1C);

    // SA1: group(r=0.2,K=64) -> feats -> 3->64->64->128 -> maxpool
    group_kernel<NPT,256><<<dim3(M1C/2, BATCH), 64>>>(pos, pos1, nidx1, cnt1, M1C, 0.04f);
    {
        const int rows = BATCH*M1C*KNB;  // 524288
        feats1_kernel<<<rows/128, 128>>>(pos, pos1, nidx1, fF);
        gemm_kernel<<<dim3(64/64, rows/64), 128>>>(fF, W1a, b1a, bA, 64, 3, 1);
        gemm_kernel<<<dim3(64/64, rows/64), 128>>>(bA, W1b, b1b, bB, 64, 64, 1);
        gemm_maxpool_kernel<<<dim3(128/64, BATCH*M1C), 128>>>(bB, W1c, b1c, x1, cnt1, 128, 64);
    }

    // FPS level 2
    fps_kernel<M1C,M2C><<<BATCH, 1024>>>(pos1, curv1, fps2);
    gather_kernel<<<(BATCH*M2C+255)/256, 256>>>(pos1, curv1, fps2, pos2, (float*)0, M1C, M2C, BATCH*M2C);

    // SA2: group(r=0.4) -> feats(131) -> 131->128->128->256 -> maxpool
    group_kernel<M1C,M1C><<<dim3(M2C/2, BATCH), 64>>>(pos1, pos2, nidx2, cnt2, M2C, 0.16f);
    {
        const int rows = BATCH*M2C*KNB;  // 131072
        feats2_kernel<<<rows/4, 128>>>(x1, pos1, pos2, nidx2, fF);
        gemm_kernel<<<dim3(128/64, rows/64), 128>>>(fF, W2a, b2a, bA, 128, 131, 1);
        gemm_kernel<<<dim3(128/64, rows/64), 128>>>(bA, W2b, b2b, bB, 128, 128, 1);
        gemm_maxpool_kernel<<<dim3(256/64, BATCH*M2C), 128>>>(bB, W2c, b2c, x2, cnt2, 256, 128);
    }

    // SA3 global: feats(259) -> 259->256->512->1024 -> max over M2
    {
        const int rows = BATCH*M2C;  // 2048
        feats3_kernel<<<rows/4, 128>>>(x2, pos2, fF);
        gemm_kernel<<<dim3(256/64, rows/64), 128>>>(fF, W3a, b3a, bA, 256, 259, 1);
        gemm_kernel<<<dim3(512/64, rows/64), 128>>>(bA, W3b, b3b, bB, 512, 256, 1);
        gemm_kernel<<<dim3(1024/64, rows/64), 128>>>(bB, W3c, b3c, bA, 1024, 512, 0);
        pool256_kernel<<<dim3(1024/256, BATCH), 256>>>(bA, gfeat);
    }

    // head
    head_kernel<<<BATCH, 256>>>(gfeat, Wh1, bh1, Wh2, bh2, Wh3, bh3, (float*)d_out);
}

// round 3
// speedup vs baseline: 1.5164x; 1.5164x over previous
#include <cuda_runtime.h>
#include <math.h>
#include <float.h>

#define BATCH 8
#define NPT   2048
#define M1C   1024
#define M2C   256
#define KNB   64
#define CURVK 10

// ---- scratch (device globals; no allocation) ----
__device__ float g_curv [BATCH*NPT];
__device__ int   g_fps1 [BATCH*M1C];
__device__ int   g_fps2 [BATCH*M2C];
__device__ float g_pos1 [BATCH*M1C*3];
__device__ float g_curv1[BATCH*M1C];
__device__ float g_pos2 [BATCH*M2C*3];
__device__ int   g_nidx1[BATCH*M1C*KNB];
__device__ int   g_cnt1 [BATCH*M1C];
__device__ int   g_nidx2[BATCH*M2C*KNB];
__device__ int   g_cnt2 [BATCH*M2C];
__device__ float g_x1   [BATCH*M1C*128];
__device__ float g_x2   [BATCH*M2C*256];
__device__ float g_gfeat[BATCH*1024];
__device__ float g_featF[2*1024*1024];                    // y1 / SA3 feats
__device__ float g_bufA [(size_t)BATCH*M1C*KNB*128];      // 268 MB
__device__ float g_bufB [(size_t)BATCH*M1C*KNB*128];      // 268 MB

// ---- curvature: 10-NN covariance eigen ratio ----
__global__ void curvature_kernel(const float* __restrict__ pos, float* __restrict__ curv)
{
    __shared__ float px[NPT], py[NPT], pz[NPT], nr[NPT];
    const int b = blockIdx.x / (NPT/128);
    const int tid = threadIdx.x;
    const float* cp = pos + (size_t)b * NPT * 3;
    for (int i = tid; i < NPT; i += 128) {
        float x = cp[3*i], y = cp[3*i+1], z = cp[3*i+2];
        px[i]=x; py[i]=y; pz[i]=z; nr[i]=x*x+y*y+z*z;
    }
    __syncthreads();
    const int i = (blockIdx.x % (NPT/128)) * 128 + tid;
    const float qx=px[i], qy=py[i], qz=pz[i], nq=nr[i];

    float td[CURVK]; int ti[CURVK];
#pragma unroll
    for (int s = 0; s < CURVK; ++s) { td[s]=3.4e38f; ti[s]=0; }
    for (int j = 0; j < NPT; ++j) {
        float d2 = nq + nr[j] - 2.0f*(qx*px[j]+qy*py[j]+qz*pz[j]);
        if (d2 < td[CURVK-1]) {
            float cd=d2; int ci=j;
#pragma unroll
            for (int s = 0; s < CURVK; ++s)
                if (cd < td[s]) { float t=td[s]; td[s]=cd; cd=t; int u=ti[s]; ti[s]=ci; ci=u; }
        }
    }
    float mx=0,my=0,mz=0;
#pragma unroll
    for (int s = 0; s < CURVK; ++s) { mx+=px[ti[s]]; my+=py[ti[s]]; mz+=pz[ti[s]]; }
    mx/=CURVK; my/=CURVK; mz/=CURVK;
    double cxx=0,cxy=0,cxz=0,cyy=0,cyz=0,czz=0;
#pragma unroll
    for (int s = 0; s < CURVK; ++s) {
        float ax=px[ti[s]]-mx, ay=py[ti[s]]-my, az=pz[ti[s]]-mz;
        cxx+=(double)ax*ax; cxy+=(double)ax*ay; cxz+=(double)ax*az;
        cyy+=(double)ay*ay; cyz+=(double)ay*az; czz+=(double)az*az;
    }
    cxx/=CURVK; cxy/=CURVK; cxz/=CURVK; cyy/=CURVK; cyz/=CURVK; czz/=CURVK;
    double tr=cxx+cyy+czz;
    double p1=cxy*cxy+cxz*cxz+cyz*cyz;
    double q=tr/3.0;
    double p2=(cxx-q)*(cxx-q)+(cyy-q)*(cyy-q)+(czz-q)*(czz-q)+2.0*p1;
    double lmin;
    if (p2 < 1e-32) lmin = q;
    else {
        double p=sqrt(p2/6.0);
        double b00=(cxx-q)/p,b11=(cyy-q)/p,b22=(czz-q)/p,b01=cxy/p,b02=cxz/p,b12=cyz/p;
        double detB=b00*(b11*b22-b12*b12)-b01*(b01*b22-b12*b02)+b02*(b01*b12-b11*b02);
        double r=fmin(1.0,fmax(-1.0,detB*0.5));
        lmin=q+2.0*p*cos(acos(r)/3.0 + 2.0943951023931953);
    }
    curv[b*NPT+i]=(float)(lmin/(tr+1e-8));
}

// ---- weighted FPS: fused update+argmax, 2 barriers/iter ----
template<int NPTS,int MOUT>
__global__ void __launch_bounds__(512) fps_kernel(const float* __restrict__ pos,
                                                  const float* __restrict__ curv,
                                                  int* __restrict__ out_idx)
{
    constexpr int THR = 512, E = NPTS/THR;
    __shared__ float px[NPTS],py[NPTS],pz[NPTS],ww[NPTS],md[NPTS];
    __shared__ float rv[16]; __shared__ int ri[16]; __shared__ int sbest;
    const int b=blockIdx.x, tid=threadIdx.x;
    const float* cp = pos + (size_t)b*NPTS*3;
    for (int i = tid; i < NPTS; i += THR) {
        px[i]=cp[3*i]; py[i]=cp[3*i+1]; pz[i]=cp[3*i+2];
        ww[i]=1.0f+10.0f*curv[b*NPTS+i];
        md[i]=FLT_MAX;
    }
    if (tid==0) out_idx[b*MOUT]=0;
    __syncthreads();
    int s = 0;
    for (int m = 1; m < MOUT; ++m) {
        const float sx=px[s], sy=py[s], sz=pz[s];
        float bv=-1.0f; int bi=0;
#pragma unroll
        for (int e = 0; e < E; ++e) {
            int i = tid + e*THR;
            float dx=px[i]-sx, dy=py[i]-sy, dz=pz[i]-sz;
            float d = fminf(md[i], dx*dx+dy*dy+dz*dz);
            md[i] = d;
            float v = d*ww[i];
            if (v>bv || (v==bv && i<bi)) { bv=v; bi=i; }
        }
#pragma unroll
        for (int off = 16; off; off >>= 1) {
            float ov=__shfl_down_sync(0xffffffffu,bv,off);
            int   oi=__shfl_down_sync(0xffffffffu,bi,off);
            if (ov>bv || (ov==bv && oi<bi)) { bv=ov; bi=oi; }
        }
        if ((tid&31)==0) { rv[tid>>5]=bv; ri[tid>>5]=bi; }
        __syncthreads();
        if (tid < 32) {
            bv = (tid<16) ? rv[tid] : -2.0f;
            bi = (tid<16) ? ri[tid] : 0x7fffffff;
#pragma unroll
            for (int off = 8; off; off >>= 1) {
                float ov=__shfl_down_sync(0xffffffffu,bv,off);
                int   oi=__shfl_down_sync(0xffffffffu,bi,off);
                if (ov>bv || (ov==bv && oi<bi)) { bv=ov; bi=oi; }
            }
            if (tid==0) { sbest=bi; out_idx[b*MOUT+m]=bi; }
        }
        __syncthreads();
        s = sbest;
    }
}

__global__ void gather_kernel(const float* __restrict__ pos, const float* __restrict__ curv,
                              const int* __restrict__ idx, float* __restrict__ opos,
                              float* __restrict__ ocurv, int npts, int mout, int total)
{
    int t = blockIdx.x*256 + threadIdx.x;
    if (t >= total) return;
    int b = t / mout, i = idx[t], src = b*npts + i;
    opos[3*t]=pos[3*src]; opos[3*t+1]=pos[3*src+1]; opos[3*t+2]=pos[3*src+2];
    if (ocurv) ocurv[t]=curv[src];
}

// ---- radius grouping: up to KNB nearest within r (warp per centroid) ----
template<int NPTS,int CAP,int CPB>
__global__ void group_kernel(const float* __restrict__ pts, const float* __restrict__ cents,
                             int* __restrict__ nidx, int* __restrict__ cnt_out,
                             int MC, float r2)
{
    __shared__ float px[NPTS],py[NPTS],pz[NPTS],nr[NPTS];
    __shared__ unsigned long long cand[CPB][CAP];
    const int b=blockIdx.y, tid=threadIdx.x;
    const float* cp = pts + (size_t)b*NPTS*3;
    for (int i = tid; i < NPTS; i += CPB*32) {
        float x=cp[3*i],y=cp[3*i+1],z=cp[3*i+2];
        px[i]=x; py[i]=y; pz[i]=z; nr[i]=x*x+y*y+z*z;
    }
    __syncthreads();
    const int w=tid>>5, lane=tid&31;
    const int c=blockIdx.x*CPB+w, cg=b*MC+c;
    const float cx=cents[3*cg],cy=cents[3*cg+1],cz=cents[3*cg+2];
    const float nc=cx*cx+cy*cy+cz*cz;
    int cnt=0;
    for (int j0 = 0; j0 < NPTS; j0 += 32) {
        int j=j0+lane;
        float d2 = nc + nr[j] - 2.0f*(cx*px[j]+cy*py[j]+cz*pz[j]);
        bool in = (d2 <= r2);
        unsigned mask = __ballot_sync(0xffffffffu, in);
        if (in) {
            int p = cnt + __popc(mask & ((1u<<lane)-1u));
            if (p < CAP) {
                unsigned ub=__float_as_uint(d2);
                ub = (ub&0x80000000u) ? ~ub : (ub|0x80000000u);
                cand[w][p] = ((unsigned long long)ub<<32) | (unsigned)j;
            }
        }
        cnt += __popc(mask);
    }
    if (cnt > CAP) cnt = CAP;
    for (int i = cnt+lane; i < CAP; i += 32) cand[w][i]=0xFFFFFFFFFFFFFFFFull;
    __syncwarp();
    for (int k = 2; k <= CAP; k <<= 1)
        for (int j = k>>1; j > 0; j >>= 1) {
            for (int i = lane; i < CAP; i += 32) {
                int ixj = i^j;
                if (ixj > i) {
                    unsigned long long a=cand[w][i], bb=cand[w][ixj];
                    if ((a>bb) == ((i&k)==0)) { cand[w][i]=bb; cand[w][ixj]=a; }
                }
            }
            __syncwarp();
        }
    int nv = cnt < KNB ? cnt : KNB;
    int fb = (nv>0) ? (int)(cand[w][0]&0xffffffffu) : 0;
    for (int i = lane; i < KNB; i += 32)
        nidx[(size_t)cg*KNB+i] = (i<nv) ? (int)(cand[w][i]&0xffffffffu) : fb;
    if (lane==0) cnt_out[cg]=nv;
}

// ---- fused SA1 layer-1: relpos -> 3x64 MLP + ReLU ----
__global__ void __launch_bounds__(256) sa1_l1_kernel(
    const float* __restrict__ pos, const float* __restrict__ pos1,
    const int* __restrict__ nidx, const float* __restrict__ W,
    const float* __restrict__ bias, float* __restrict__ out)
{
    __shared__ float w[192], bs[64];
    const int tid = threadIdx.x;
    if (tid < 192) w[tid] = W[tid];
    if (tid < 64)  bs[tid] = bias[tid];
    __syncthreads();
    const int e = blockIdx.x*64 + (tid>>2);
    const int c = e/KNB, b = c/M1C;
    const int src = b*NPT + nidx[e];
    const float rx = pos[3*src]  -pos1[3*c];
    const float ry = pos[3*src+1]-pos1[3*c+1];
    const float rz = pos[3*src+2]-pos1[3*c+2];
    const int c0 = (tid&3)*16;
    float o[16];
#pragma unroll
    for (int j = 0; j < 16; ++j) {
        int n = c0 + j;
        o[j] = fmaxf(rx*w[n] + ry*w[64+n] + rz*w[128+n] + bs[n], 0.f);
    }
    float* op = out + (size_t)e*64 + c0;
#pragma unroll
    for (int j = 0; j < 4; ++j)
        *(float4*)(op + 4*j) = make_float4(o[4*j],o[4*j+1],o[4*j+2],o[4*j+3]);
}

// ---- SA2 edge kernel: out = relu(y1[src] + rel @ W2a[128:131] ) ----
__global__ void __launch_bounds__(256) sa2_edge_kernel(
    const float* __restrict__ y1, const float* __restrict__ pos1,
    const float* __restrict__ pos2, const int* __restrict__ nidx,
    const float* __restrict__ W, float* __restrict__ out)
{
    const int e = blockIdx.x*2 + (threadIdx.x>>7);
    const int n = threadIdx.x & 127;
    const int c = e/KNB, b = c/M2C;
    const int gp = b*M1C + nidx[e];
    const float rx = pos1[3*gp]  -pos2[3*c];
    const float ry = pos1[3*gp+1]-pos2[3*c+1];
    const float rz = pos1[3*gp+2]-pos2[3*c+2];
    float v = y1[(size_t)gp*128+n] + rx*W[128*128+n] + ry*W[129*128+n] + rz*W[130*128+n];
    out[(size_t)e*128+n] = fmaxf(v, 0.f);
}

__global__ void feats3_kernel(const float* __restrict__ x2, const float* __restrict__ pos2,
                              float* __restrict__ feats)
{
    int row = blockIdx.x*4 + (threadIdx.x>>5), lane = threadIdx.x&31;
    const float* xs = x2 + (size_t)row*256;
    float* f = feats + (size_t)row*259;
    for (int i = lane; i < 256; i += 32) f[i]=xs[i];
    if (lane < 3) f[256+lane]=pos2[row*3+lane];
}

// ---- fp32 GEMM: 128xTN tile, 256 threads, double-buffered smem ----
template<int TN>
__global__ void __launch_bounds__(256) gemm128_kernel(
    const float* __restrict__ A, const float* __restrict__ W,
    const float* __restrict__ bias, float* __restrict__ C,
    int N, int Kc, int relu)
{
    constexpr int JN = TN/16;            // 8 or 4 cols/thread
    constexpr int WL = (TN*16)/256;      // W loads/thread per slab
    __shared__ float As[2][16*128];
    __shared__ float Ws[2][16*TN];
    const int tid = threadIdx.x;
    const int tx = tid & 15, ty = tid >> 4;
    const int bm = blockIdx.y*128, bn = blockIdx.x*TN;
    const int arow = tid >> 1, akk = (tid & 1)*8;
    const int nkt = (Kc + 15) >> 4;

    float acc[8][JN];
#pragma unroll
    for (int i=0;i<8;++i)
#pragma unroll
        for (int j=0;j<JN;++j) acc[i][j]=0.f;

    // slab 0 direct to smem
#pragma unroll
    for (int j = 0; j < 8; ++j) {
        int k = akk + j;
        As[0][k*128 + arow] = (k < Kc) ? A[(size_t)(bm+arow)*Kc + k] : 0.f;
    }
#pragma unroll
    for (int r = 0; r < WL; ++r) {
        int e = tid + r*256;
        int n = e % TN, k = e / TN;
        Ws[0][k*TN + n] = (k < Kc) ? W[(size_t)k*N + bn + n] : 0.f;
    }
    __syncthreads();

    for (int kt = 0; kt < nkt; ++kt) {
        const int cur = kt & 1;
        float ra[8], rw[WL];
        if (kt+1 < nkt) {
            const int k0 = (kt+1) << 4;
#pragma unroll
            for (int j = 0; j < 8; ++j) {
                int k = k0 + akk + j;
                ra[j] = (k < Kc) ? A[(size_t)(bm+arow)*Kc + k] : 0.f;
            }
#pragma unroll
            for (int r = 0; r < WL; ++r) {
                int e = tid + r*256;
                int n = e % TN, k = k0 + e/TN;
                rw[r] = (k < Kc) ? W[(size_t)k*N + bn + n] : 0.f;
            }
        }
#pragma unroll
        for (int k = 0; k < 16; ++k) {
            float4 a0 = *(const float4*)&As[cur][k*128 + ty*4];
            float4 a1 = *(const float4*)&As[cur][k*128 + ty*4 + 64];
            float av[8] = {a0.x,a0.y,a0.z,a0.w,a1.x,a1.y,a1.z,a1.w};
            float bv[JN];
            float4 b0 = *(const float4*)&Ws[cur][k*TN + tx*4];
            bv[0]=b0.x; bv[1]=b0.y; bv[2]=b0.z; bv[3]=b0.w;
            if (TN == 128) {
                float4 b1 = *(const float4*)&Ws[cur][k*TN + tx*4 + 64];
                bv[4]=b1.x; bv[5]=b1.y; bv[6]=b1.z; bv[7]=b1.w;
            }
#pragma unroll
            for (int i=0;i<8;++i)
#pragma unroll
                for (int j=0;j<JN;++j) acc[i][j] += av[i]*bv[j];
        }
        if (kt+1 < nkt) {
#pragma unroll
            for (int j = 0; j < 8; ++j) As[cur^1][(akk+j)*128 + arow] = ra[j];
#pragma unroll
            for (int r = 0; r < WL; ++r) {
                int e = tid + r*256;
                Ws[cur^1][(e/TN)*TN + (e%TN)] = rw[r];
            }
            __syncthreads();
        }
    }

    float bb[JN];
#pragma unroll
    for (int j = 0; j < 4; ++j) bb[j] = bias[bn + tx*4 + j];
    if (TN == 128)
#pragma unroll
        for (int j = 4; j < 8; ++j) bb[j] = bias[bn + tx*4 + 64 + j-4];
#pragma unroll
    for (int i = 0; i < 8; ++i) {
        int row = bm + ((i<4) ? ty*4+i : ty*4+i-4+64);
        float v[JN];
#pragma unroll
        for (int j = 0; j < JN; ++j) {
            v[j] = acc[i][j] + bb[j];
            if (relu) v[j] = fmaxf(v[j], 0.f);
        }
        *(float4*)&C[(size_t)row*N + bn + tx*4] = make_float4(v[0],v[1],v[2],v[3]);
        if (TN == 128)
            *(float4*)&C[(size_t)row*N + bn + tx*4 + 64] = make_float4(v[4],v[5],v[6],v[7]);
    }
}

// ---- masked max over 64-row groups ----
__global__ void maxpool_kernel(const float* __restrict__ X, float* __restrict__ out,
                               const int* __restrict__ cnt, int N)
{
    const int g = blockIdx.y;
    const int col = blockIdx.x*128 + threadIdx.x;
    const int cv = cnt[g];
    float m = -FLT_MAX;
    const float* xp = X + (size_t)g*64*N + col;
    for (int r = 0; r < cv; ++r) m = fmaxf(m, xp[(size_t)r*N]);
    out[(size_t)g*N + col] = (cv>0) ? m : 0.f;
}

// ---- global max pool over M2 rows ----
__global__ void pool256_kernel(const float* __restrict__ g, float* __restrict__ gfeat)
{
    int b = blockIdx.y, f = blockIdx.x*256 + threadIdx.x;
    float m = -FLT_MAX;
    for (int r = 0; r < M2C; ++r)
        m = fmaxf(m, g[(size_t)(b*M2C+r)*1024 + f]);
    gfeat[b*1024+f]=m;
}

// ---- head MLP + log_softmax ----
__global__ void head_kernel(const float* __restrict__ gfeat,
                            const float* __restrict__ Wh1, const float* __restrict__ bh1,
                            const float* __restrict__ Wh2, const float* __restrict__ bh2,
                            const float* __restrict__ Wh3, const float* __restrict__ bh3,
                            float* __restrict__ out)
{
    __shared__ float gf[1024], h1[512], h2[256], lg[10];
    const int b=blockIdx.x, tid=threadIdx.x;
    for (int i = tid; i < 1024; i += 256) gf[i]=gfeat[b*1024+i];
    __syncthreads();
    for (int n = tid; n < 512; n += 256) {
        float s = bh1[n];
        for (int k = 0; k < 1024; ++k) s += gf[k]*Wh1[(size_t)k*512+n];
        h1[n]=fmaxf(s,0.f);
    }
    __syncthreads();
    { float s = bh2[tid];
      for (int k = 0; k < 512; ++k) s += h1[k]*Wh2[(size_t)k*256+tid];
      h2[tid]=fmaxf(s,0.f); }
    __syncthreads();
    if (tid < 10) {
        float s = bh3[tid];
        for (int k = 0; k < 256; ++k) s += h2[k]*Wh3[k*10+tid];
        lg[tid]=s;
    }
    __syncthreads();
    if (tid == 0) {
        float m=lg[0];
        for (int j=1;j<10;++j) m=fmaxf(m,lg[j]);
        float se=0.f;
        for (int j=0;j<10;++j) se+=expf(lg[j]-m);
        float l=logf(se);
        for (int j=0;j<10;++j) out[b*10+j]=lg[j]-m-l;
    }
}

extern "C" void kernel_launch(void* const* d_in, const int* in_sizes, int n_in,
                              void* d_out, int out_size)
{
    const float* pos=(const float*)d_in[0];
    const float *W1a=(const float*)d_in[1],  *b1a=(const float*)d_in[2];
    const float *W1b=(const float*)d_in[3],  *b1b=(const float*)d_in[4];
    const float *W1c=(const float*)d_in[5],  *b1c=(const float*)d_in[6];
    const float *W2a=(const float*)d_in[7],  *b2a=(const float*)d_in[8];
    const float *W2b=(const float*)d_in[9],  *b2b=(const float*)d_in[10];
    const float *W2c=(const float*)d_in[11], *b2c=(const float*)d_in[12];
    const float *W3a=(const float*)d_in[13], *b3a=(const float*)d_in[14];
    const float *W3b=(const float*)d_in[15], *b3b=(const float*)d_in[16];
    const float *W3c=(const float*)d_in[17], *b3c=(const float*)d_in[18];
    const float *Wh1=(const float*)d_in[19], *bh1=(const float*)d_in[20];
    const float *Wh2=(const float*)d_in[21], *bh2=(const float*)d_in[22];
    const float *Wh3=(const float*)d_in[23], *bh3=(const float*)d_in[24];

    float *curv,*pos1,*curv1,*pos2,*x1,*x2,*gfeat,*fF,*bA,*bB;
    int *fps1,*fps2,*nidx1,*cnt1,*nidx2,*cnt2;
    cudaGetSymbolAddress((void**)&curv, g_curv);
    cudaGetSymbolAddress((void**)&fps1, g_fps1);
    cudaGetSymbolAddress((void**)&fps2, g_fps2);
    cudaGetSymbolAddress((void**)&pos1, g_pos1);
    cudaGetSymbolAddress((void**)&curv1,g_curv1);
    cudaGetSymbolAddress((void**)&pos2, g_pos2);
    cudaGetSymbolAddress((void**)&nidx1,g_nidx1);
    cudaGetSymbolAddress((void**)&cnt1, g_cnt1);
    cudaGetSymbolAddress((void**)&nidx2,g_nidx2);
    cudaGetSymbolAddress((void**)&cnt2, g_cnt2);
    cudaGetSymbolAddress((void**)&x1,   g_x1);
    cudaGetSymbolAddress((void**)&x2,   g_x2);
    cudaGetSymbolAddress((void**)&gfeat,g_gfeat);
    cudaGetSymbolAddress((void**)&fF,   g_featF);
    cudaGetSymbolAddress((void**)&bA,   g_bufA);
    cudaGetSymbolAddress((void**)&bB,   g_bufB);

    // curvature + FPS level 1
    curvature_kernel<<<BATCH*(NPT/128), 128>>>(pos, curv);
    fps_kernel<NPT,M1C><<<BATCH, 512>>>(pos, curv, fps1);
    gather_kernel<<<(BATCH*M1C+255)/256, 256>>>(pos, curv, fps1, pos1, curv1, NPT, M1C, BATCH*M1C);

    // SA1: group(r=0.2) -> fused L1 -> 64->64 -> 64->128 -> maxpool
    group_kernel<NPT,128,8><<<dim3(M1C/8, BATCH), 256>>>(pos, pos1, nidx1, cnt1, M1C, 0.04f);
    {
        const int rows = BATCH*M1C*KNB;  // 524288
        sa1_l1_kernel<<<rows/64, 256>>>(pos, pos1, nidx1, W1a, b1a, bA);
        gemm128_kernel<64> <<<dim3(1, rows/128), 256>>>(bA, W1b, b1b, bB, 64, 64, 1);
        gemm128_kernel<128><<<dim3(1, rows/128), 256>>>(bB, W1c, b1c, bA, 128, 64, 0);
        maxpool_kernel<<<dim3(1, BATCH*M1C), 128>>>(bA, x1, cnt1, 128);
    }

    // FPS level 2
    fps_kernel<M1C,M2C><<<BATCH, 512>>>(pos1, curv1, fps2);
    gather_kernel<<<(BATCH*M2C+255)/256, 256>>>(pos1, curv1, fps2, pos2, (float*)0, M1C, M2C, BATCH*M2C);

    // SA2: group(r=0.4) -> dedup L1 (y1 per source + rel term per edge) -> 128->128 -> 128->256 -> maxpool
    group_kernel<M1C,512,4><<<dim3(M2C/4, BATCH), 128>>>(pos1, pos2, nidx2, cnt2, M2C, 0.16f);
    {
        const int rows = BATCH*M2C*KNB;  // 131072
        gemm128_kernel<128><<<dim3(1, BATCH*M1C/128), 256>>>(x1, W2a, b2a, fF, 128, 128, 0);
        sa2_edge_kernel<<<rows/2, 256>>>(fF, pos1, pos2, nidx2, W2a, bA);
        gemm128_kernel<128><<<dim3(1, rows/128), 256>>>(bA, W2b, b2b, bB, 128, 128, 1);
        gemm128_kernel<128><<<dim3(2, rows/128), 256>>>(bB, W2c, b2c, bA, 256, 128, 0);
        maxpool_kernel<<<dim3(2, BATCH*M2C), 128>>>(bA, x2, cnt2, 256);
    }

    // SA3 global: feats(259) -> 259->256 -> 256->512 -> 512->1024 -> max over M2
    {
        const int rows = BATCH*M2C;  // 2048
        feats3_kernel<<<rows/4, 128>>>(x2, pos2, fF);
        gemm128_kernel<64><<<dim3(4,  rows/128), 256>>>(fF, W3a, b3a, bA, 256, 259, 1);
        gemm128_kernel<64><<<dim3(8,  rows/128), 256>>>(bA, W3b, b3b, bB, 512, 256, 1);
        gemm128_kernel<64><<<dim3(16, rows/128), 256>>>(bB, W3c, b3c, bA, 1024, 512, 0);
        pool256_kernel<<<dim3(4, BATCH), 256>>>(bA, gfeat);
    }

    // head
    head_kernel<<<BATCH, 256>>>(gfeat, Wh1, bh1, Wh2, bh2, Wh3, bh3, (float*)d_out);
}

// round 4
// speedup vs baseline: 1.5671x; 1.0335x over previous
#include <cuda_runtime.h>
#include <cuda_bf16.h>
#include <math.h>
#include <float.h>

#define BATCH 8
#define NPT   2048
#define M1C   1024
#define M2C   256
#define KNB   64
#define CURVK 10

// ---- scratch (device globals; no allocation) ----
__device__ float g_curv [BATCH*NPT];
__device__ int   g_fps1 [BATCH*M1C];
__device__ int   g_fps2 [BATCH*M2C];
__device__ float g_pos1 [BATCH*M1C*3];
__device__ float g_curv1[BATCH*M1C];
__device__ float g_pos2 [BATCH*M2C*3];
__device__ int   g_nidx1[BATCH*M1C*KNB];
__device__ int   g_cnt1 [BATCH*M1C];
__device__ int   g_nidx2[BATCH*M2C*KNB];
__device__ int   g_cnt2 [BATCH*M2C];
__device__ float g_x1   [BATCH*M1C*128];
__device__ float g_x2   [BATCH*M2C*256];
__device__ float g_gfeat[BATCH*1024];
__device__ float g_featF[2*1024*1024];                    // y1 / SA3 feats
__device__ float g_bufA [(size_t)BATCH*M1C*KNB*128];      // 268 MB fp32 (L3 outs, SA1)
__device__ float g_bufB [4*1024*1024];                    // SA3 intermediates
__device__ __nv_bfloat16 g_hiA[(size_t)BATCH*M1C*KNB*64]; // 67 MB split planes
__device__ __nv_bfloat16 g_loA[(size_t)BATCH*M1C*KNB*64];
__device__ __nv_bfloat16 g_hiB[(size_t)BATCH*M1C*KNB*64];
__device__ __nv_bfloat16 g_loB[(size_t)BATCH*M1C*KNB*64];
__device__ __nv_bfloat16 g_wthi[32768], g_wtlo[32768];    // split transposed W (<=128x256)

__device__ __forceinline__ void splitf(float v, __nv_bfloat16& h, __nv_bfloat16& l) {
    h = __float2bfloat16(v);
    l = __float2bfloat16(v - __bfloat162float(h));
}

// ---- curvature: 10-NN covariance eigen ratio ----
__global__ void curvature_kernel(const float* __restrict__ pos, float* __restrict__ curv)
{
    __shared__ float px[NPT], py[NPT], pz[NPT], nr[NPT];
    const int b = blockIdx.x / (NPT/128);
    const int tid = threadIdx.x;
    const float* cp = pos + (size_t)b * NPT * 3;
    for (int i = tid; i < NPT; i += 128) {
        float x = cp[3*i], y = cp[3*i+1], z = cp[3*i+2];
        px[i]=x; py[i]=y; pz[i]=z; nr[i]=x*x+y*y+z*z;
    }
    __syncthreads();
    const int i = (blockIdx.x % (NPT/128)) * 128 + tid;
    const float qx=px[i], qy=py[i], qz=pz[i], nq=nr[i];

    float td[CURVK]; int ti[CURVK];
#pragma unroll
    for (int s = 0; s < CURVK; ++s) { td[s]=3.4e38f; ti[s]=0; }
    for (int j = 0; j < NPT; ++j) {
        float d2 = nq + nr[j] - 2.0f*(qx*px[j]+qy*py[j]+qz*pz[j]);
        if (d2 < td[CURVK-1]) {
            float cd=d2; int ci=j;
#pragma unroll
            for (int s = 0; s < CURVK; ++s)
                if (cd < td[s]) { float t=td[s]; td[s]=cd; cd=t; int u=ti[s]; ti[s]=ci; ci=u; }
        }
    }
    float mx=0,my=0,mz=0;
#pragma unroll
    for (int s = 0; s < CURVK; ++s) { mx+=px[ti[s]]; my+=py[ti[s]]; mz+=pz[ti[s]]; }
    mx/=CURVK; my/=CURVK; mz/=CURVK;
    double cxx=0,cxy=0,cxz=0,cyy=0,cyz=0,czz=0;
#pragma unroll
    for (int s = 0; s < CURVK; ++s) {
        float ax=px[ti[s]]-mx, ay=py[ti[s]]-my, az=pz[ti[s]]-mz;
        cxx+=(double)ax*ax; cxy+=(double)ax*ay; cxz+=(double)ax*az;
        cyy+=(double)ay*ay; cyz+=(double)ay*az; czz+=(double)az*az;
    }
    cxx/=CURVK; cxy/=CURVK; cxz/=CURVK; cyy/=CURVK; cyz/=CURVK; czz/=CURVK;
    double tr=cxx+cyy+czz;
    double p1=cxy*cxy+cxz*cxz+cyz*cyz;
    double q=tr/3.0;
    double p2=(cxx-q)*(cxx-q)+(cyy-q)*(cyy-q)+(czz-q)*(czz-q)+2.0*p1;
    double lmin;
    if (p2 < 1e-32) lmin = q;
    else {
        double p=sqrt(p2/6.0);
        double b00=(cxx-q)/p,b11=(cyy-q)/p,b22=(czz-q)/p,b01=cxy/p,b02=cxz/p,b12=cyz/p;
        double detB=b00*(b11*b22-b12*b12)-b01*(b01*b22-b12*b02)+b02*(b01*b12-b11*b02);
        double r=fmin(1.0,fmax(-1.0,detB*0.5));
        lmin=q+2.0*p*cos(acos(r)/3.0 + 2.0943951023931953);
    }
    curv[b*NPT+i]=(float)(lmin/(tr+1e-8));
}

// ---- weighted FPS: fused update+argmax, 2 barriers/iter ----
template<int NPTS,int MOUT>
__global__ void __launch_bounds__(512) fps_kernel(const float* __restrict__ pos,
                                                  const float* __restrict__ curv,
                                                  int* __restrict__ out_idx)
{
    constexpr int THR = 512, E = NPTS/THR;
    __shared__ float px[NPTS],py[NPTS],pz[NPTS],ww[NPTS],md[NPTS];
    __shared__ float rv[16]; __shared__ int ri[16]; __shared__ int sbest;
    const int b=blockIdx.x, tid=threadIdx.x;
    const float* cp = pos + (size_t)b*NPTS*3;
    for (int i = tid; i < NPTS; i += THR) {
        px[i]=cp[3*i]; py[i]=cp[3*i+1]; pz[i]=cp[3*i+2];
        ww[i]=1.0f+10.0f*curv[b*NPTS+i];
        md[i]=FLT_MAX;
    }
    if (tid==0) out_idx[b*MOUT]=0;
    __syncthreads();
    int s = 0;
    for (int m = 1; m < MOUT; ++m) {
        const float sx=px[s], sy=py[s], sz=pz[s];
        float bv=-1.0f; int bi=0;
#pragma unroll
        for (int e = 0; e < E; ++e) {
            int i = tid + e*THR;
            float dx=px[i]-sx, dy=py[i]-sy, dz=pz[i]-sz;
            float d = fminf(md[i], dx*dx+dy*dy+dz*dz);
            md[i] = d;
            float v = d*ww[i];
            if (v>bv || (v==bv && i<bi)) { bv=v; bi=i; }
        }
#pragma unroll
        for (int off = 16; off; off >>= 1) {
            float ov=__shfl_down_sync(0xffffffffu,bv,off);
            int   oi=__shfl_down_sync(0xffffffffu,bi,off);
            if (ov>bv || (ov==bv && oi<bi)) { bv=ov; bi=oi; }
        }
        if ((tid&31)==0) { rv[tid>>5]=bv; ri[tid>>5]=bi; }
        __syncthreads();
        if (tid < 32) {
            bv = (tid<16) ? rv[tid] : -2.0f;
            bi = (tid<16) ? ri[tid] : 0x7fffffff;
#pragma unroll
            for (int off = 8; off; off >>= 1) {
                float ov=__shfl_down_sync(0xffffffffu,bv,off);
                int   oi=__shfl_down_sync(0xffffffffu,bi,off);
                if (ov>bv || (ov==bv && oi<bi)) { bv=ov; bi=oi; }
            }
            if (tid==0) { sbest=bi; out_idx[b*MOUT+m]=bi; }
        }
        __syncthreads();
        s = sbest;
    }
}

__global__ void gather_kernel(const float* __restrict__ pos, const float* __restrict__ curv,
                              const int* __restrict__ idx, float* __restrict__ opos,
                              float* __restrict__ ocurv, int npts, int mout, int total)
{
    int t = blockIdx.x*256 + threadIdx.x;
    if (t >= total) return;
    int b = t / mout, i = idx[t], src = b*npts + i;
    opos[3*t]=pos[3*src]; opos[3*t+1]=pos[3*src+1]; opos[3*t+2]=pos[3*src+2];
    if (ocurv) ocurv[t]=curv[src];
}

// ---- radius grouping: up to KNB nearest within r (warp per centroid) ----
template<int NPTS,int CAP,int CPB>
__global__ void group_kernel(const float* __restrict__ pts, const float* __restrict__ cents,
                             int* __restrict__ nidx, int* __restrict__ cnt_out,
                             int MC, float r2)
{
    __shared__ float px[NPTS],py[NPTS],pz[NPTS],nr[NPTS];
    __shared__ unsigned long long cand[CPB][CAP];
    const int b=blockIdx.y, tid=threadIdx.x;
    const float* cp = pts + (size_t)b*NPTS*3;
    for (int i = tid; i < NPTS; i += CPB*32) {
        float x=cp[3*i],y=cp[3*i+1],z=cp[3*i+2];
        px[i]=x; py[i]=y; pz[i]=z; nr[i]=x*x+y*y+z*z;
    }
    __syncthreads();
    const int w=tid>>5, lane=tid&31;
    const int c=blockIdx.x*CPB+w, cg=b*MC+c;
    const float cx=cents[3*cg],cy=cents[3*cg+1],cz=cents[3*cg+2];
    const float nc=cx*cx+cy*cy+cz*cz;
    int cnt=0;
    for (int j0 = 0; j0 < NPTS; j0 += 32) {
        int j=j0+lane;
        float d2 = nc + nr[j] - 2.0f*(cx*px[j]+cy*py[j]+cz*pz[j]);
        bool in = (d2 <= r2);
        unsigned mask = __ballot_sync(0xffffffffu, in);
        if (in) {
            int p = cnt + __popc(mask & ((1u<<lane)-1u));
            if (p < CAP) {
                unsigned ub=__float_as_uint(d2);
                ub = (ub&0x80000000u) ? ~ub : (ub|0x80000000u);
                cand[w][p] = ((unsigned long long)ub<<32) | (unsigned)j;
            }
        }
        cnt += __popc(mask);
    }
    if (cnt > CAP) cnt = CAP;
    for (int i = cnt+lane; i < CAP; i += 32) cand[w][i]=0xFFFFFFFFFFFFFFFFull;
    __syncwarp();
    for (int k = 2; k <= CAP; k <<= 1)
        for (int j = k>>1; j > 0; j >>= 1) {
            for (int i = lane; i < CAP; i += 32) {
                int ixj = i^j;
                if (ixj > i) {
                    unsigned long long a=cand[w][i], bb=cand[w][ixj];
                    if ((a>bb) == ((i&k)==0)) { cand[w][i]=bb; cand[w][ixj]=a; }
                }
            }
            __syncwarp();
        }
    int nv = cnt < KNB ? cnt : KNB;
    int fb = (nv>0) ? (int)(cand[w][0]&0xffffffffu) : 0;
    for (int i = lane; i < KNB; i += 32)
        nidx[(size_t)cg*KNB+i] = (i<nv) ? (int)(cand[w][i]&0xffffffffu) : fb;
    if (lane==0) cnt_out[cg]=nv;
}

// ---- fused SA1 layer-1: relpos -> 3x64 MLP + ReLU -> split bf16 planes ----
__global__ void __launch_bounds__(256) sa1_l1_kernel(
    const float* __restrict__ pos, const float* __restrict__ pos1,
    const int* __restrict__ nidx, const float* __restrict__ W,
    const float* __restrict__ bias,
    __nv_bfloat16* __restrict__ ohi, __nv_bfloat16* __restrict__ olo)
{
    __shared__ float w[192], bs[64];
    const int tid = threadIdx.x;
    if (tid < 192) w[tid] = W[tid];
    if (tid < 64)  bs[tid] = bias[tid];
    __syncthreads();
    const int e = blockIdx.x*64 + (tid>>2);
    const int c = e/KNB, b = c/M1C;
    const int src = b*NPT + nidx[e];
    const float rx = pos[3*src]  -pos1[3*c];
    const float ry = pos[3*src+1]-pos1[3*c+1];
    const float rz = pos[3*src+2]-pos1[3*c+2];
    const int c0 = (tid&3)*16;
#pragma unroll
    for (int j = 0; j < 16; j += 2) {
        int n = c0 + j;
        float v0 = fmaxf(rx*w[n]   + ry*w[64+n]   + rz*w[128+n]   + bs[n],   0.f);
        float v1 = fmaxf(rx*w[n+1] + ry*w[64+n+1] + rz*w[128+n+1] + bs[n+1], 0.f);
        __nv_bfloat16 h0,l0,h1,l1;
        splitf(v0,h0,l0); splitf(v1,h1,l1);
        __nv_bfloat162 hh; hh.x=h0; hh.y=h1;
        __nv_bfloat162 ll; ll.x=l0; ll.y=l1;
        *(__nv_bfloat162*)&ohi[(size_t)e*64 + n] = hh;
        *(__nv_bfloat162*)&olo[(size_t)e*64 + n] = ll;
    }
}

// ---- SA2 edge kernel: relu(y1[src] + rel @ W2a[128:131]) -> split planes ----
__global__ void __launch_bounds__(256) sa2_edge_kernel(
    const float* __restrict__ y1, const float* __restrict__ pos1,
    const float* __restrict__ pos2, const int* __restrict__ nidx,
    const float* __restrict__ W,
    __nv_bfloat16* __restrict__ ohi, __nv_bfloat16* __restrict__ olo)
{
    const int e = blockIdx.x*2 + (threadIdx.x>>7);
    const int n = threadIdx.x & 127;
    const int c = e/KNB, b = c/M2C;
    const int gp = b*M1C + nidx[e];
    const float rx = pos1[3*gp]  -pos2[3*c];
    const float ry = pos1[3*gp+1]-pos2[3*c+1];
    const float rz = pos1[3*gp+2]-pos2[3*c+2];
    float v = y1[(size_t)gp*128+n] + rx*W[128*128+n] + ry*W[129*128+n] + rz*W[130*128+n];
    v = fmaxf(v, 0.f);
    __nv_bfloat16 h,l; splitf(v,h,l);
    ohi[(size_t)e*128+n]=h; olo[(size_t)e*128+n]=l;
}

// ---- weight prep: W[K][N] fp32 -> transposed split planes Wt[n*K+k] ----
__global__ void wprep_kernel(const float* __restrict__ W,
                             __nv_bfloat16* __restrict__ hi, __nv_bfloat16* __restrict__ lo,
                             int K, int N)
{
    int t = blockIdx.x*256 + threadIdx.x;
    if (t >= K*N) return;
    int n = t / K, k = t % K;
    __nv_bfloat16 h,l; splitf(W[(size_t)k*N + n], h, l);
    hi[t]=h; lo[t]=l;
}

// ---- tensor-core GEMM: bf16 3-product split, 128x64 block tile ----
__device__ __forceinline__ void mma16816(float* c, const unsigned* a, const unsigned* b) {
    asm volatile(
      "mma.sync.aligned.m16n8k16.row.col.f32.bf16.bf16.f32 "
      "{%0,%1,%2,%3}, {%4,%5,%6,%7}, {%8,%9}, {%0,%1,%2,%3};\n"
      : "+f"(c[0]), "+f"(c[1]), "+f"(c[2]), "+f"(c[3])
      : "r"(a[0]), "r"(a[1]), "r"(a[2]), "r"(a[3]), "r"(b[0]), "r"(b[1]));
}

__global__ void __launch_bounds__(256) mma_gemm_kernel(
    const __nv_bfloat16* __restrict__ Ahi, const __nv_bfloat16* __restrict__ Alo,
    const __nv_bfloat16* __restrict__ Whi, const __nv_bfloat16* __restrict__ Wlo,
    const float* __restrict__ bias,
    float* __restrict__ outF,
    __nv_bfloat16* __restrict__ outHi, __nv_bfloat16* __restrict__ outLo,
    int N, int K, int relu)
{
    __shared__ __nv_bfloat16 AsH[128][34], AsL[128][34], WsH[64][34], WsL[64][34];
    const int tid = threadIdx.x;
    const int lane = tid & 31, wid = tid >> 5;
    const int wm = wid & 3, wn = wid >> 2;        // 4 x 2 warp grid
    const int bm = blockIdx.y*128, bn = blockIdx.x*64;
    const int tcol = (tid & 15)*2, trow = tid >> 4;

    float acc[2][4][4];
#pragma unroll
    for (int mf=0; mf<2; ++mf)
#pragma unroll
        for (int nf=0; nf<4; ++nf)
#pragma unroll
            for (int q=0; q<4; ++q) acc[mf][nf][q]=0.f;

    for (int k0 = 0; k0 < K; k0 += 32) {
#pragma unroll
        for (int p = 0; p < 8; ++p) {
            int r = trow + p*16;
            size_t ga = (size_t)(bm + r)*K + k0 + tcol;
            *(unsigned*)&AsH[r][tcol] = *(const unsigned*)&Ahi[ga];
            *(unsigned*)&AsL[r][tcol] = *(const unsigned*)&Alo[ga];
        }
#pragma unroll
        for (int p = 0; p < 4; ++p) {
            int n = trow + p*16;
            size_t gw = (size_t)(bn + n)*K + k0 + tcol;
            *(unsigned*)&WsH[n][tcol] = *(const unsigned*)&Whi[gw];
            *(unsigned*)&WsL[n][tcol] = *(const unsigned*)&Wlo[gw];
        }
        __syncthreads();
#pragma unroll
        for (int ks = 0; ks < 2; ++ks) {
            const int kk = ks*16 + (lane&3)*2;
            unsigned ah[2][4], al[2][4], bh[4][2], bl[4][2];
#pragma unroll
            for (int mf=0; mf<2; ++mf) {
                int r = wm*32 + mf*16 + (lane>>2);
                ah[mf][0]=*(const unsigned*)&AsH[r][kk];
                ah[mf][1]=*(const unsigned*)&AsH[r+8][kk];
                ah[mf][2]=*(const unsigned*)&AsH[r][kk+8];
                ah[mf][3]=*(const unsigned*)&AsH[r+8][kk+8];
                al[mf][0]=*(const unsigned*)&AsL[r][kk];
                al[mf][1]=*(const unsigned*)&AsL[r+8][kk];
                al[mf][2]=*(const unsigned*)&AsL[r][kk+8];
                al[mf][3]=*(const unsigned*)&AsL[r+8][kk+8];
            }
#pragma unroll
            for (int nf=0; nf<4; ++nf) {
                int n = wn*32 + nf*8 + (lane>>2);
                bh[nf][0]=*(const unsigned*)&WsH[n][kk];
                bh[nf][1]=*(const unsigned*)&WsH[n][kk+8];
                bl[nf][0]=*(const unsigned*)&WsL[n][kk];
                bl[nf][1]=*(const unsigned*)&WsL[n][kk+8];
            }
#pragma unroll
            for (int mf=0; mf<2; ++mf)
#pragma unroll
                for (int nf=0; nf<4; ++nf) {
                    mma16816(acc[mf][nf], ah[mf], bh[nf]);
                    mma16816(acc[mf][nf], ah[mf], bl[nf]);
                    mma16816(acc[mf][nf], al[mf], bh[nf]);
                }
        }
        __syncthreads();
    }

#pragma unroll
    for (int mf=0; mf<2; ++mf)
#pragma unroll
        for (int nf=0; nf<4; ++nf) {
            int r = bm + wm*32 + mf*16 + (lane>>2);
            int c = bn + wn*32 + nf*8 + (lane&3)*2;
            float b0 = bias[c], b1 = bias[c+1];
            float v00 = acc[mf][nf][0]+b0, v01 = acc[mf][nf][1]+b1;
            float v10 = acc[mf][nf][2]+b0, v11 = acc[mf][nf][3]+b1;
            if (relu) {
                v00=fmaxf(v00,0.f); v01=fmaxf(v01,0.f);
                v10=fmaxf(v10,0.f); v11=fmaxf(v11,0.f);
            }
            if (outF) {
                outF[(size_t)r*N + c]   = v00; outF[(size_t)r*N + c+1]   = v01;
                outF[(size_t)(r+8)*N+c] = v10; outF[(size_t)(r+8)*N+c+1] = v11;
            }
            if (outHi) {
                __nv_bfloat16 h0,l0,h1,l1;
                splitf(v00,h0,l0); splitf(v01,h1,l1);
                __nv_bfloat162 hh; hh.x=h0; hh.y=h1;
                __nv_bfloat162 ll; ll.x=l0; ll.y=l1;
                *(__nv_bfloat162*)&outHi[(size_t)r*N + c] = hh;
                *(__nv_bfloat162*)&outLo[(size_t)r*N + c] = ll;
                splitf(v10,h0,l0); splitf(v11,h1,l1);
                hh.x=h0; hh.y=h1; ll.x=l0; ll.y=l1;
                *(__nv_bfloat162*)&outHi[(size_t)(r+8)*N + c] = hh;
                *(__nv_bfloat162*)&outLo[(size_t)(r+8)*N + c] = ll;
            }
        }
}

// ---- fp32 GEMM: 128xTN tile, 256 threads, double-buffered smem ----
template<int TN>
__global__ void __launch_bounds__(256) gemm128_kernel(
    const float* __restrict__ A, const float* __restrict__ W,
    const float* __restrict__ bias, float* __restrict__ C,
    int N, int Kc, int relu)
{
    constexpr int JN = TN/16;
    constexpr int WL = (TN*16)/256;
    __shared__ float As[2][16*128];
    __shared__ float Ws[2][16*TN];
    const int tid = threadIdx.x;
    const int tx = tid & 15, ty = tid >> 4;
    const int bm = blockIdx.y*128, bn = blockIdx.x*TN;
    const int arow = tid >> 1, akk = (tid & 1)*8;
    const int nkt = (Kc + 15) >> 4;

    float acc[8][JN];
#pragma unroll
    for (int i=0;i<8;++i)
#pragma unroll
        for (int j=0;j<JN;++j) acc[i][j]=0.f;

#pragma unroll
    for (int j = 0; j < 8; ++j) {
        int k = akk + j;
        As[0][k*128 + arow] = (k < Kc) ? A[(size_t)(bm+arow)*Kc + k] : 0.f;
    }
#pragma unroll
    for (int r = 0; r < WL; ++r) {
        int e = tid + r*256;
        int n = e % TN, k = e / TN;
        Ws[0][k*TN + n] = (k < Kc) ? W[(size_t)k*N + bn + n] : 0.f;
    }
    __syncthreads();

    for (int kt = 0; kt < nkt; ++kt) {
        const int cur = kt & 1;
        float ra[8], rw[WL];
        if (kt+1 < nkt) {
            const int k0 = (kt+1) << 4;
#pragma unroll
            for (int j = 0; j < 8; ++j) {
                int k = k0 + akk + j;
                ra[j] = (k < Kc) ? A[(size_t)(bm+arow)*Kc + k] : 0.f;
            }
#pragma unroll
            for (int r = 0; r < WL; ++r) {
                int e = tid + r*256;
                int n = e % TN, k = k0 + e/TN;
                rw[r] = (k < Kc) ? W[(size_t)k*N + bn + n] : 0.f;
            }
        }
#pragma unroll
        for (int k = 0; k < 16; ++k) {
            float4 a0 = *(const float4*)&As[cur][k*128 + ty*4];
            float4 a1 = *(const float4*)&As[cur][k*128 + ty*4 + 64];
            float av[8] = {a0.x,a0.y,a0.z,a0.w,a1.x,a1.y,a1.z,a1.w};
            float bv[JN];
            float4 b0 = *(const float4*)&Ws[cur][k*TN + tx*4];
            bv[0]=b0.x; bv[1]=b0.y; bv[2]=b0.z; bv[3]=b0.w;
            if (TN == 128) {
                float4 b1 = *(const float4*)&Ws[cur][k*TN + tx*4 + 64];
                bv[4]=b1.x; bv[5]=b1.y; bv[6]=b1.z; bv[7]=b1.w;
            }
#pragma unroll
            for (int i=0;i<8;++i)
#pragma unroll
                for (int j=0;j<JN;++j) acc[i][j] += av[i]*bv[j];
        }
        if (kt+1 < nkt) {
#pragma unroll
            for (int j = 0; j < 8; ++j) As[cur^1][(akk+j)*128 + arow] = ra[j];
#pragma unroll
            for (int r = 0; r < WL; ++r) {
                int e = tid + r*256;
                Ws[cur^1][(e/TN)*TN + (e%TN)] = rw[r];
            }
            __syncthreads();
        }
    }

    float bb[JN];
#pragma unroll
    for (int j = 0; j < 4; ++j) bb[j] = bias[bn + tx*4 + j];
    if (TN == 128)
#pragma unroll
        for (int j = 4; j < 8; ++j) bb[j] = bias[bn + tx*4 + 64 + j-4];
#pragma unroll
    for (int i = 0; i < 8; ++i) {
        int row = bm + ((i<4) ? ty*4+i : ty*4+i-4+64);
        float v[JN];
#pragma unroll
        for (int j = 0; j < JN; ++j) {
            v[j] = acc[i][j] + bb[j];
            if (relu) v[j] = fmaxf(v[j], 0.f);
        }
        *(float4*)&C[(size_t)row*N + bn + tx*4] = make_float4(v[0],v[1],v[2],v[3]);
        if (TN == 128)
            *(float4*)&C[(size_t)row*N + bn + tx*4 + 64] = make_float4(v[4],v[5],v[6],v[7]);
    }
}

// ---- masked max over 64-row groups ----
__global__ void maxpool_kernel(const float* __restrict__ X, float* __restrict__ out,
                               const int* __restrict__ cnt, int N)
{
    const int g = blockIdx.y;
    const int col = blockIdx.x*128 + threadIdx.x;
    const int cv = cnt[g];
    float m = -FLT_MAX;
    const float* xp = X + (size_t)g*64*N + col;
    for (int r = 0; r < cv; ++r) m = fmaxf(m, xp[(size_t)r*N]);
    out[(size_t)g*N + col] = (cv>0) ? m : 0.f;
}

__global__ void feats3_kernel(const float* __restrict__ x2, const float* __restrict__ pos2,
                              float* __restrict__ feats)
{
    int row = blockIdx.x*4 + (threadIdx.x>>5), lane = threadIdx.x&31;
    const float* xs = x2 + (size_t)row*256;
    float* f = feats + (size_t)row*259;
    for (int i = lane; i < 256; i += 32) f[i]=xs[i];
    if (lane < 3) f[256+lane]=pos2[row*3+lane];
}

__global__ void pool256_kernel(const float* __restrict__ g, float* __restrict__ gfeat)
{
    int b = blockIdx.y, f = blockIdx.x*256 + threadIdx.x;
    float m = -FLT_MAX;
    for (int r = 0; r < M2C; ++r)
        m = fmaxf(m, g[(size_t)(b*M2C+r)*1024 + f]);
    gfeat[b*1024+f]=m;
}

__global__ void head_kernel(const float* __restrict__ gfeat,
                            const float* __restrict__ Wh1, const float* __restrict__ bh1,
                            const float* __restrict__ Wh2, const float* __restrict__ bh2,
                            const float* __restrict__ Wh3, const float* __restrict__ bh3,
                            float* __restrict__ out)
{
    __shared__ float gf[1024], h1[512], h2[256], lg[10];
    const int b=blockIdx.x, tid=threadIdx.x;
    for (int i = tid; i < 1024; i += 256) gf[i]=gfeat[b*1024+i];
    __syncthreads();
    for (int n = tid; n < 512; n += 256) {
        float s = bh1[n];
        for (int k = 0; k < 1024; ++k) s += gf[k]*Wh1[(size_t)k*512+n];
        h1[n]=fmaxf(s,0.f);
    }
    __syncthreads();
    { float s = bh2[tid];
      for (int k = 0; k < 512; ++k) s += h1[k]*Wh2[(size_t)k*256+tid];
      h2[tid]=fmaxf(s,0.f); }
    __syncthreads();
    if (tid < 10) {
        float s = bh3[tid];
        for (int k = 0; k < 256; ++k) s += h2[k]*Wh3[k*10+tid];
        lg[tid]=s;
    }
    __syncthreads();
    if (tid == 0) {
        float m=lg[0];
        for (int j=1;j<10;++j) m=fmaxf(m,lg[j]);
        float se=0.f;
        for (int j=0;j<10;++j) se+=expf(lg[j]-m);
        float l=logf(se);
        for (int j=0;j<10;++j) out[b*10+j]=lg[j]-m-l;
    }
}

extern "C" void kernel_launch(void* const* d_in, const int* in_sizes, int n_in,
                              void* d_out, int out_size)
{
    const float* pos=(const float*)d_in[0];
    const float *W1a=(const float*)d_in[1],  *b1a=(const float*)d_in[2];
    const float *W1b=(const float*)d_in[3],  *b1b=(const float*)d_in[4];
    const float *W1c=(const float*)d_in[5],  *b1c=(const float*)d_in[6];
    const float *W2a=(const float*)d_in[7],  *b2a=(const float*)d_in[8];
    const float *W2b=(const float*)d_in[9],  *b2b=(const float*)d_in[10];
    const float *W2c=(const float*)d_in[11], *b2c=(const float*)d_in[12];
    const float *W3a=(const float*)d_in[13], *b3a=(const float*)d_in[14];
    const float *W3b=(const float*)d_in[15], *b3b=(const float*)d_in[16];
    const float *W3c=(const float*)d_in[17], *b3c=(const float*)d_in[18];
    const float *Wh1=(const float*)d_in[19], *bh1=(const float*)d_in[20];
    const float *Wh2=(const float*)d_in[21], *bh2=(const float*)d_in[22];
    const float *Wh3=(const float*)d_in[23], *bh3=(const float*)d_in[24];

    float *curv,*pos1,*curv1,*pos2,*x1,*x2,*gfeat,*fF,*bA,*bB;
    int *fps1,*fps2,*nidx1,*cnt1,*nidx2,*cnt2;
    __nv_bfloat16 *hiA,*loA,*hiB,*loB,*wthi,*wtlo;
    cudaGetSymbolAddress((void**)&curv, g_curv);
    cudaGetSymbolAddress((void**)&fps1, g_fps1);
    cudaGetSymbolAddress((void**)&fps2, g_fps2);
    cudaGetSymbolAddress((void**)&pos1, g_pos1);
    cudaGetSymbolAddress((void**)&curv1,g_curv1);
    cudaGetSymbolAddress((void**)&pos2, g_pos2);
    cudaGetSymbolAddress((void**)&nidx1,g_nidx1);
    cudaGetSymbolAddress((void**)&cnt1, g_cnt1);
    cudaGetSymbolAddress((void**)&nidx2,g_nidx2);
    cudaGetSymbolAddress((void**)&cnt2, g_cnt2);
    cudaGetSymbolAddress((void**)&x1,   g_x1);
    cudaGetSymbolAddress((void**)&x2,   g_x2);
    cudaGetSymbolAddress((void**)&gfeat,g_gfeat);
    cudaGetSymbolAddress((void**)&fF,   g_featF);
    cudaGetSymbolAddress((void**)&bA,   g_bufA);
    cudaGetSymbolAddress((void**)&bB,   g_bufB);
    cudaGetSymbolAddress((void**)&hiA,  g_hiA);
    cudaGetSymbolAddress((void**)&loA,  g_loA);
    cudaGetSymbolAddress((void**)&hiB,  g_hiB);
    cudaGetSymbolAddress((void**)&loB,  g_loB);
    cudaGetSymbolAddress((void**)&wthi, g_wthi);
    cudaGetSymbolAddress((void**)&wtlo, g_wtlo);

    // curvature + FPS level 1
    curvature_kernel<<<BATCH*(NPT/128), 128>>>(pos, curv);
    fps_kernel<NPT,M1C><<<BATCH, 512>>>(pos, curv, fps1);
    gather_kernel<<<(BATCH*M1C+255)/256, 256>>>(pos, curv, fps1, pos1, curv1, NPT, M1C, BATCH*M1C);

    // SA1: group(r=0.2) -> fused L1(split) -> mma 64->64 -> mma 64->128 -> maxpool
    group_kernel<NPT,128,8><<<dim3(M1C/8, BATCH), 256>>>(pos, pos1, nidx1, cnt1, M1C, 0.04f);
    {
        const int rows = BATCH*M1C*KNB;  // 524288
        sa1_l1_kernel<<<rows/64, 256>>>(pos, pos1, nidx1, W1a, b1a, hiA, loA);
        wprep_kernel<<<(64*64+255)/256, 256>>>(W1b, wthi, wtlo, 64, 64);
        mma_gemm_kernel<<<dim3(1, rows/128), 256>>>(hiA, loA, wthi, wtlo, b1b,
                                                    (float*)0, hiB, loB, 64, 64, 1);
        wprep_kernel<<<(64*128+255)/256, 256>>>(W1c, wthi, wtlo, 64, 128);
        mma_gemm_kernel<<<dim3(2, rows/128), 256>>>(hiB, loB, wthi, wtlo, b1c,
                                                    bA, (__nv_bfloat16*)0, (__nv_bfloat16*)0, 128, 64, 0);
        maxpool_kernel<<<dim3(1, BATCH*M1C), 128>>>(bA, x1, cnt1, 128);
    }

    // FPS level 2
    fps_kernel<M1C,M2C><<<BATCH, 512>>>(pos1, curv1, fps2);
    gather_kernel<<<(BATCH*M2C+255)/256, 256>>>(pos1, curv1, fps2, pos2, (float*)0, M1C, M2C, BATCH*M2C);

    // SA2: group(r=0.4) -> y1 + edge(split) -> mma 128->128 -> mma 128->256 -> maxpool
    group_kernel<M1C,512,4><<<dim3(M2C/4, BATCH), 128>>>(pos1, pos2, nidx2, cnt2, M2C, 0.16f);
    {
        const int rows = BATCH*M2C*KNB;  // 131072
        gemm128_kernel<128><<<dim3(1, BATCH*M1C/128), 256>>>(x1, W2a, b2a, fF, 128, 128, 0);
        sa2_edge_kernel<<<rows/2, 256>>>(fF, pos1, pos2, nidx2, W2a, hiA, loA);
        wprep_kernel<<<(128*128+255)/256, 256>>>(W2b, wthi, wtlo, 128, 128);
        mma_gemm_kernel<<<dim3(2, rows/128), 256>>>(hiA, loA, wthi, wtlo, b2b,
                                                    (float*)0, hiB, loB, 128, 128, 1);
        wprep_kernel<<<(128*256+255)/256, 256>>>(W2c, wthi, wtlo, 128, 256);
        mma_gemm_kernel<<<dim3(4, rows/128), 256>>>(hiB, loB, wthi, wtlo, b2c,
                                                    bA, (__nv_bfloat16*)0, (__nv_bfloat16*)0, 256, 128, 0);
        maxpool_kernel<<<dim3(2, BATCH*M2C), 128>>>(bA, x2, cnt2, 256);
    }

    // SA3 global: feats(259) -> 259->256 -> 256->512 -> 512->1024 -> max over M2
    {
        const int rows = BATCH*M2C;  // 2048
        feats3_kernel<<<rows/4, 128>>>(x2, pos2, fF);
        gemm128_kernel<64><<<dim3(4,  rows/128), 256>>>(fF, W3a, b3a, bA, 256, 259, 1);
        gemm128_kernel<64><<<dim3(8,  rows/128), 256>>>(bA, W3b, b3b, bB, 512, 256, 1);
        gemm128_kernel<64><<<dim3(16, rows/128), 256>>>(bB, W3c, b3c, bA, 1024, 512, 0);
        pool256_kernel<<<dim3(4, BATCH), 256>>>(bA, gfeat);
    }

    // head
    head_kernel<<<BATCH, 256>>>(gfeat, Wh1, bh1, Wh2, bh2, Wh3, bh3, (float*)d_out);
}

// round 5
// speedup vs baseline: 2.5515x; 1.6281x over previous
#include <cuda_runtime.h>
#include <cuda_bf16.h>
#include <math.h>
#include <float.h>

#define BATCH 8
#define NPT   2048
#define M1C   1024
#define M2C   256
#define KNB   64
#define CURVK 10

// ---- scratch (device globals; no allocation) ----
__device__ float g_curv [BATCH*NPT];
__device__ int   g_fps1 [BATCH*M1C];
__device__ int   g_fps2 [BATCH*M2C];
__device__ float g_pos1 [BATCH*M1C*3];
__device__ float g_curv1[BATCH*M1C];
__device__ float g_pos2 [BATCH*M2C*3];
__device__ int   g_nidx1[BATCH*M1C*KNB];
__device__ int   g_cnt1 [BATCH*M1C];
__device__ int   g_nidx2[BATCH*M2C*KNB];
__device__ int   g_cnt2 [BATCH*M2C];
__device__ float g_x1   [BATCH*M1C*128];
__device__ float g_x2   [BATCH*M2C*256];
__device__ float g_gfeat[BATCH*1024];
__device__ float g_featF[2*1024*1024];        // y1 (8192x128) / SA3 feats
__device__ float g_bufA [2*1024*1024];        // SA3 intermediates
__device__ float g_bufB [1*1024*1024];
__device__ __nv_bfloat16 g_w1bh[4096],  g_w1bl[4096];    // W1b  [64][64]
__device__ __nv_bfloat16 g_w1ch[8192],  g_w1cl[8192];    // W1c  [128][64]
__device__ __nv_bfloat16 g_w2bh[16384], g_w2bl[16384];   // W2b  [128][128]
__device__ __nv_bfloat16 g_w2ch[32768], g_w2cl[32768];   // W2c  [256][128]

__device__ __forceinline__ void splitf(float v, __nv_bfloat16& h, __nv_bfloat16& l) {
    h = __float2bfloat16(v);
    l = __float2bfloat16(v - __bfloat162float(h));
}

__device__ __forceinline__ void mma16816(float* c, const unsigned* a, const unsigned* b) {
    asm volatile(
      "mma.sync.aligned.m16n8k16.row.col.f32.bf16.bf16.f32 "
      "{%0,%1,%2,%3}, {%4,%5,%6,%7}, {%8,%9}, {%0,%1,%2,%3};\n"
      : "+f"(c[0]), "+f"(c[1]), "+f"(c[2]), "+f"(c[3])
      : "r"(a[0]), "r"(a[1]), "r"(a[2]), "r"(a[3]), "r"(b[0]), "r"(b[1]));
}

// shared mma block: 128 rows x (NF*8 cols per warp-half), 3-product bf16 split
template<int NF,int K16,int S>
__device__ __forceinline__ void mma_block(
    float (&acc)[2][8][4],
    const __nv_bfloat16* AsH, const __nv_bfloat16* AsL,
    const __nv_bfloat16* WH,  const __nv_bfloat16* WL,
    int wm, int wnbase, int lane)
{
#pragma unroll
    for (int k16=0;k16<K16;++k16){
        const int kk=k16*16+(lane&3)*2;
        unsigned ah[2][4], al[2][4];
#pragma unroll
        for (int mf=0;mf<2;++mf){
            int r=wm*32+mf*16+(lane>>2);
            ah[mf][0]=*(const unsigned*)&AsH[r*S+kk];
            ah[mf][1]=*(const unsigned*)&AsH[(r+8)*S+kk];
            ah[mf][2]=*(const unsigned*)&AsH[r*S+kk+8];
            ah[mf][3]=*(const unsigned*)&AsH[(r+8)*S+kk+8];
            al[mf][0]=*(const unsigned*)&AsL[r*S+kk];
            al[mf][1]=*(const unsigned*)&AsL[(r+8)*S+kk];
            al[mf][2]=*(const unsigned*)&AsL[r*S+kk+8];
            al[mf][3]=*(const unsigned*)&AsL[(r+8)*S+kk+8];
        }
#pragma unroll
        for (int nf=0;nf<NF;++nf){
            int n=wnbase+nf*8+(lane>>2);
            unsigned bh[2]={*(const unsigned*)&WH[n*S+kk], *(const unsigned*)&WH[n*S+kk+8]};
            unsigned bl[2]={*(const unsigned*)&WL[n*S+kk], *(const unsigned*)&WL[n*S+kk+8]};
#pragma unroll
            for (int mf=0;mf<2;++mf){
                mma16816(acc[mf][nf], ah[mf], bh);
                mma16816(acc[mf][nf], ah[mf], bl);
                mma16816(acc[mf][nf], al[mf], bh);
            }
        }
    }
}

// ---- curvature: 10-NN covariance eigen ratio ----
__global__ void curvature_kernel(const float* __restrict__ pos, float* __restrict__ curv)
{
    __shared__ float px[NPT], py[NPT], pz[NPT], nr[NPT];
    const int b = blockIdx.x / (NPT/128);
    const int tid = threadIdx.x;
    const float* cp = pos + (size_t)b * NPT * 3;
    for (int i = tid; i < NPT; i += 128) {
        float x = cp[3*i], y = cp[3*i+1], z = cp[3*i+2];
        px[i]=x; py[i]=y; pz[i]=z; nr[i]=x*x+y*y+z*z;
    }
    __syncthreads();
    const int i = (blockIdx.x % (NPT/128)) * 128 + tid;
    const float qx=px[i], qy=py[i], qz=pz[i], nq=nr[i];

    float td[CURVK]; int ti[CURVK];
#pragma unroll
    for (int s = 0; s < CURVK; ++s) { td[s]=3.4e38f; ti[s]=0; }
    for (int j = 0; j < NPT; ++j) {
        float d2 = nq + nr[j] - 2.0f*(qx*px[j]+qy*py[j]+qz*pz[j]);
        if (d2 < td[CURVK-1]) {
            float cd=d2; int ci=j;
#pragma unroll
            for (int s = 0; s < CURVK; ++s)
                if (cd < td[s]) { float t=td[s]; td[s]=cd; cd=t; int u=ti[s]; ti[s]=ci; ci=u; }
        }
    }
    float mx=0,my=0,mz=0;
#pragma unroll
    for (int s = 0; s < CURVK; ++s) { mx+=px[ti[s]]; my+=py[ti[s]]; mz+=pz[ti[s]]; }
    mx/=CURVK; my/=CURVK; mz/=CURVK;
    double cxx=0,cxy=0,cxz=0,cyy=0,cyz=0,czz=0;
#pragma unroll
    for (int s = 0; s < CURVK; ++s) {
        float ax=px[ti[s]]-mx, ay=py[ti[s]]-my, az=pz[ti[s]]-mz;
        cxx+=(double)ax*ax; cxy+=(double)ax*ay; cxz+=(double)ax*az;
        cyy+=(double)ay*ay; cyz+=(double)ay*az; czz+=(double)az*az;
    }
    cxx/=CURVK; cxy/=CURVK; cxz/=CURVK; cyy/=CURVK; cyz/=CURVK; czz/=CURVK;
    double tr=cxx+cyy+czz;
    double p1=cxy*cxy+cxz*cxz+cyz*cyz;
    double q=tr/3.0;
    double p2=(cxx-q)*(cxx-q)+(cyy-q)*(cyy-q)+(czz-q)*(czz-q)+2.0*p1;
    double lmin;
    if (p2 < 1e-32) lmin = q;
    else {
        double p=sqrt(p2/6.0);
        double b00=(cxx-q)/p,b11=(cyy-q)/p,b22=(czz-q)/p,b01=cxy/p,b02=cxz/p,b12=cyz/p;
        double detB=b00*(b11*b22-b12*b12)-b01*(b01*b22-b12*b02)+b02*(b01*b12-b11*b02);
        double r=fmin(1.0,fmax(-1.0,detB*0.5));
        lmin=q+2.0*p*cos(acos(r)/3.0 + 2.0943951023931953);
    }
    curv[b*NPT+i]=(float)(lmin/(tr+1e-8));
}

// ---- weighted FPS: register-resident, redux argmax, 1 barrier/iter ----
template<int NPTS,int MOUT>
__global__ void __launch_bounds__(256) fps_kernel(const float* __restrict__ pos,
                                                  const float* __restrict__ curv,
                                                  int* __restrict__ out_idx)
{
    constexpr int THR=256, E=NPTS/THR;
    __shared__ unsigned long long wkey[2][8];
    const int b=blockIdx.x, tid=threadIdx.x, lane=tid&31, wid=tid>>5;
    const float* cp = pos + (size_t)b*NPTS*3;
    float px[E],py[E],pz[E],ww[E],md[E];
#pragma unroll
    for (int e=0;e<E;++e){
        int i=tid+e*THR;
        px[e]=cp[3*i]; py[e]=cp[3*i+1]; pz[e]=cp[3*i+2];
        ww[e]=1.0f+10.0f*curv[b*NPTS+i];
        md[e]=FLT_MAX;
    }
    if (tid==0) out_idx[b*MOUT]=0;
    float sx=cp[0], sy=cp[1], sz=cp[2];
    for (int m=1;m<MOUT;++m){
        float bv=-1.f; int bi=0;
#pragma unroll
        for (int e=0;e<E;++e){
            int i=tid+e*THR;
            float dx=px[e]-sx, dy=py[e]-sy, dz=pz[e]-sz;
            float d=fminf(md[e], dx*dx+dy*dy+dz*dz);
            md[e]=d;
            float v=d*ww[e];
            if (v>bv){ bv=v; bi=i; }       // i strictly increasing per thread -> first max kept
        }
        unsigned hv=__float_as_uint(bv);   // bv >= 0 -> bit order == float order
        unsigned hm=__reduce_max_sync(0xffffffffu, hv);
        unsigned lm=__reduce_max_sync(0xffffffffu, (hv==hm)? ~(unsigned)bi : 0u);
        if (lane==0) wkey[m&1][wid]=((unsigned long long)hm<<32)|lm;
        __syncthreads();
        unsigned long long k2 = (lane<8)? wkey[m&1][lane] : 0ull;
        unsigned h2=(unsigned)(k2>>32), l2=(unsigned)k2;
        unsigned hm2=__reduce_max_sync(0xffffffffu, h2);
        unsigned lm2=__reduce_max_sync(0xffffffffu, (h2==hm2)? l2 : 0u);
        int s=(int)(~lm2);
        if (tid==0) out_idx[b*MOUT+m]=s;
        sx=cp[3*s]; sy=cp[3*s+1]; sz=cp[3*s+2];
    }
}

__global__ void gather_kernel(const float* __restrict__ pos, const float* __restrict__ curv,
                              const int* __restrict__ idx, float* __restrict__ opos,
                              float* __restrict__ ocurv, int npts, int mout, int total)
{
    int t = blockIdx.x*256 + threadIdx.x;
    if (t >= total) return;
    int b = t / mout, i = idx[t], src = b*npts + i;
    opos[3*t]=pos[3*src]; opos[3*t+1]=pos[3*src+1]; opos[3*t+2]=pos[3*src+2];
    if (ocurv) ocurv[t]=curv[src];
}

// ---- radius grouping ----
template<int NPTS,int CAP,int CPB>
__global__ void group_kernel(const float* __restrict__ pts, const float* __restrict__ cents,
                             int* __restrict__ nidx, int* __restrict__ cnt_out,
                             int MC, float r2)
{
    __shared__ float px[NPTS],py[NPTS],pz[NPTS],nr[NPTS];
    __shared__ unsigned long long cand[CPB][CAP];
    const int b=blockIdx.y, tid=threadIdx.x;
    const float* cp = pts + (size_t)b*NPTS*3;
    for (int i = tid; i < NPTS; i += CPB*32) {
        float x=cp[3*i],y=cp[3*i+1],z=cp[3*i+2];
        px[i]=x; py[i]=y; pz[i]=z; nr[i]=x*x+y*y+z*z;
    }
    __syncthreads();
    const int w=tid>>5, lane=tid&31;
    const int c=blockIdx.x*CPB+w, cg=b*MC+c;
    const float cx=cents[3*cg],cy=cents[3*cg+1],cz=cents[3*cg+2];
    const float nc=cx*cx+cy*cy+cz*cz;
    int cnt=0;
    for (int j0 = 0; j0 < NPTS; j0 += 32) {
        int j=j0+lane;
        float d2 = nc + nr[j] - 2.0f*(cx*px[j]+cy*py[j]+cz*pz[j]);
        bool in = (d2 <= r2);
        unsigned mask = __ballot_sync(0xffffffffu, in);
        if (in) {
            int p = cnt + __popc(mask & ((1u<<lane)-1u));
            if (p < CAP) {
                unsigned ub=__float_as_uint(d2);
                ub = (ub&0x80000000u) ? ~ub : (ub|0x80000000u);
                cand[w][p] = ((unsigned long long)ub<<32) | (unsigned)j;
            }
        }
        cnt += __popc(mask);
    }
    if (cnt > CAP) cnt = CAP;
    for (int i = cnt+lane; i < CAP; i += 32) cand[w][i]=0xFFFFFFFFFFFFFFFFull;
    __syncwarp();
    for (int k = 2; k <= CAP; k <<= 1)
        for (int j = k>>1; j > 0; j >>= 1) {
            for (int i = lane; i < CAP; i += 32) {
                int ixj = i^j;
                if (ixj > i) {
                    unsigned long long a=cand[w][i], bb=cand[w][ixj];
                    if ((a>bb) == ((i&k)==0)) { cand[w][i]=bb; cand[w][ixj]=a; }
                }
            }
            __syncwarp();
        }
    int nv = cnt < KNB ? cnt : KNB;
    int fb = (nv>0) ? (int)(cand[w][0]&0xffffffffu) : 0;
    for (int i = lane; i < KNB; i += 32)
        nidx[(size_t)cg*KNB+i] = (i<nv) ? (int)(cand[w][i]&0xffffffffu) : fb;
    if (lane==0) cnt_out[cg]=nv;
}

// ---- weight prep: W[K][N] fp32 -> transposed split planes [N][K] ----
__global__ void wprep_kernel(const float* __restrict__ W,
                             __nv_bfloat16* __restrict__ hi, __nv_bfloat16* __restrict__ lo,
                             int K, int N)
{
    int t = blockIdx.x*256 + threadIdx.x;
    if (t >= K*N) return;
    int n = t / K, k = t % K;
    __nv_bfloat16 h,l; splitf(W[(size_t)k*N + n], h, l);
    hi[t]=h; lo[t]=l;
}

// ---- fused SA1: 2 centroids/block, rel->L1->L2->L3->masked max ----
__global__ void __launch_bounds__(256) sa1_fused_kernel(
    const float* __restrict__ pos, const float* __restrict__ pos1,
    const int* __restrict__ nidx, const int* __restrict__ cnt,
    const float* __restrict__ W1a, const float* __restrict__ b1a,
    const __nv_bfloat16* __restrict__ wbh, const __nv_bfloat16* __restrict__ wbl,
    const float* __restrict__ b1b,
    const __nv_bfloat16* __restrict__ wch, const __nv_bfloat16* __restrict__ wcl,
    const float* __restrict__ b1c,
    float* __restrict__ x1)
{
    constexpr int S = 72;   // K=64 + 8 pad -> conflict-free fragment reads
    extern __shared__ __align__(16) char sm1[];
    __nv_bfloat16* AsH = (__nv_bfloat16*)sm1;
    __nv_bfloat16* AsL = AsH + 128*S;
    __nv_bfloat16* WcH = AsL + 128*S;
    __nv_bfloat16* WcL = WcH + 128*S;
    __nv_bfloat16* WbH = WcL + 128*S;
    __nv_bfloat16* WbL = WbH + 64*S;
    float* w1s   = (float*)(WbL + 64*S);   // 192 W1a + 64 b1a
    float* colmax= w1s + 256;              // [8][128]

    const int tid=threadIdx.x, lane=tid&31, wid=tid>>5;
    const int wm=wid&3, wn=wid>>2;
    const int cg0 = blockIdx.x*2;

    for (int t=tid; t<64*64;  t+=256){ int n=t>>6,k=t&63; WbH[n*S+k]=wbh[t]; WbL[n*S+k]=wbl[t]; }
    for (int t=tid; t<128*64; t+=256){ int n=t>>6,k=t&63; WcH[n*S+k]=wch[t]; WcL[n*S+k]=wcl[t]; }
    if (tid<192) w1s[tid]=W1a[tid];
    else if (tid<256) w1s[tid]=b1a[tid-192];
    __syncthreads();

    // L1 build (scalar): 128 rows x 64
    {
        const int row=tid>>1, h0=(tid&1)*32;
        const int cg = cg0 + (row>>6);
        const int p  = nidx[cg*64 + (row&63)];
        const int src = (cg>>10)*NPT + p;
        const float rx = pos[3*src]  -pos1[3*cg];
        const float ry = pos[3*src+1]-pos1[3*cg+1];
        const float rz = pos[3*src+2]-pos1[3*cg+2];
#pragma unroll
        for (int j=0;j<32;++j){
            int n=h0+j;
            float v=fmaxf(rx*w1s[n]+ry*w1s[64+n]+rz*w1s[128+n]+w1s[192+n],0.f);
            splitf(v, AsH[row*S+n], AsL[row*S+n]);
        }
    }
    __syncthreads();

    float acc[2][8][4];
    // ---- L2: K=64, N=64 ----
#pragma unroll
    for (int mf=0;mf<2;++mf)
#pragma unroll
        for (int nf=0;nf<4;++nf)
#pragma unroll
            for (int q=0;q<4;++q) acc[mf][nf][q]=0.f;
    mma_block<4,4,S>(acc, AsH, AsL, WbH, WbL, wm, wn*32, lane);
    __syncthreads();
    // store h2 (bias+relu, split) back into As
#pragma unroll
    for (int mf=0;mf<2;++mf)
#pragma unroll
        for (int nf=0;nf<4;++nf){
            int r=wm*32+mf*16+(lane>>2);
            int c=wn*32+nf*8+(lane&3)*2;
            float b0=b1b[c], b1v=b1b[c+1];
            float v00=fmaxf(acc[mf][nf][0]+b0,0.f), v01=fmaxf(acc[mf][nf][1]+b1v,0.f);
            float v10=fmaxf(acc[mf][nf][2]+b0,0.f), v11=fmaxf(acc[mf][nf][3]+b1v,0.f);
            __nv_bfloat16 h0,l0,h1,l1;
            splitf(v00,h0,l0); splitf(v01,h1,l1);
            __nv_bfloat162 hh,ll;
            hh.x=h0; hh.y=h1; ll.x=l0; ll.y=l1;
            *(__nv_bfloat162*)&AsH[r*S+c]=hh; *(__nv_bfloat162*)&AsL[r*S+c]=ll;
            splitf(v10,h0,l0); splitf(v11,h1,l1);
            hh.x=h0; hh.y=h1; ll.x=l0; ll.y=l1;
            *(__nv_bfloat162*)&AsH[(r+8)*S+c]=hh; *(__nv_bfloat162*)&AsL[(r+8)*S+c]=ll;
        }
    __syncthreads();

    // ---- L3: K=64, N=128 ----
#pragma unroll
    for (int mf=0;mf<2;++mf)
#pragma unroll
        for (int nf=0;nf<8;++nf)
#pragma unroll
            for (int q=0;q<4;++q) acc[mf][nf][q]=0.f;
    mma_block<8,4,S>(acc, AsH, AsL, WcH, WcL, wm, wn*64, lane);

    const int cv0=cnt[cg0], cv1=cnt[cg0+1];
#pragma unroll
    for (int nf=0;nf<8;++nf){
        int c=wn*64+nf*8+(lane&3)*2;
        float b0=b1c[c], b1v=b1c[c+1];
        float m0=-FLT_MAX, m1=-FLT_MAX;
#pragma unroll
        for (int mf=0;mf<2;++mf){
            int r=wm*32+mf*16+(lane>>2);
            int cv=(r>>6)?cv1:cv0;
            int rl=r&63;
            if (rl   < cv){ m0=fmaxf(m0,acc[mf][nf][0]+b0); m1=fmaxf(m1,acc[mf][nf][1]+b1v); }
            if (rl+8 < cv){ m0=fmaxf(m0,acc[mf][nf][2]+b0); m1=fmaxf(m1,acc[mf][nf][3]+b1v); }
        }
#pragma unroll
        for (int off=4; off<32; off<<=1){
            m0=fmaxf(m0,__shfl_xor_sync(0xffffffffu,m0,off));
            m1=fmaxf(m1,__shfl_xor_sync(0xffffffffu,m1,off));
        }
        if (lane<4){ colmax[wid*128+c]=m0; colmax[wid*128+c+1]=m1; }
    }
    __syncthreads();
    {
        int cent=tid>>7, col=tid&127;
        int wb=(col>>6)*4 + cent*2;
        float m=fmaxf(colmax[wb*128+col], colmax[(wb+1)*128+col]);
        int cv = cent? cv1:cv0;
        x1[(size_t)(cg0+cent)*128+col] = cv? m : 0.f;
    }
}

// ---- fused SA2: 2 centroids/block, y1-gather+rel->relu->L2->L3(2 halves)->masked max ----
__global__ void __launch_bounds__(256) sa2_fused_kernel(
    const float* __restrict__ y1, const float* __restrict__ pos1,
    const float* __restrict__ pos2, const int* __restrict__ nidx,
    const int* __restrict__ cnt, const float* __restrict__ W2a,
    const __nv_bfloat16* __restrict__ wbh, const __nv_bfloat16* __restrict__ wbl,
    const float* __restrict__ b2b,
    const __nv_bfloat16* __restrict__ wch, const __nv_bfloat16* __restrict__ wcl,
    const float* __restrict__ b2c,
    float* __restrict__ x2)
{
    constexpr int S = 136;  // K=128 + 8 pad
    extern __shared__ __align__(16) char sm2[];
    __nv_bfloat16* AsH = (__nv_bfloat16*)sm2;
    __nv_bfloat16* AsL = AsH + 128*S;
    __nv_bfloat16* WsH = AsL + 128*S;
    __nv_bfloat16* WsL = WsH + 128*S;
    float* w2a3  = (float*)(WsL + 128*S);  // 384
    float* colmax= w2a3 + 384;             // [8][128]

    const int tid=threadIdx.x, lane=tid&31, wid=tid>>5;
    const int wm=wid&3, wn=wid>>2;
    const int cg0 = blockIdx.x*2;

    for (int t=tid; t<384; t+=256) w2a3[t]=W2a[16384+t];
    for (int t=tid; t<16384; t+=256){ int n=t>>7,k=t&127; WsH[n*S+k]=wbh[t]; WsL[n*S+k]=wbl[t]; }
    __syncthreads();

    // input build: 128 rows x 128
    {
        const int row=tid>>1, h0=(tid&1)*64;
        const int cg = cg0 + (row>>6);
        const int gp = (cg>>8)*M1C + nidx[cg*64 + (row&63)];
        const float rx = pos1[3*gp]  -pos2[3*cg];
        const float ry = pos1[3*gp+1]-pos2[3*cg+1];
        const float rz = pos1[3*gp+2]-pos2[3*cg+2];
        const float* yr = y1 + (size_t)gp*128;
#pragma unroll
        for (int j=0;j<64;++j){
            int n=h0+j;
            float v=fmaxf(yr[n]+rx*w2a3[n]+ry*w2a3[128+n]+rz*w2a3[256+n],0.f);
            splitf(v, AsH[row*S+n], AsL[row*S+n]);
        }
    }
    __syncthreads();

    float acc[2][8][4];
    // ---- L2: K=128, N=128 ----
#pragma unroll
    for (int mf=0;mf<2;++mf)
#pragma unroll
        for (int nf=0;nf<8;++nf)
#pragma unroll
            for (int q=0;q<4;++q) acc[mf][nf][q]=0.f;
    mma_block<8,8,S>(acc, AsH, AsL, WsH, WsL, wm, wn*64, lane);
    __syncthreads();
    // h2 -> As (bias+relu, split)
#pragma unroll
    for (int mf=0;mf<2;++mf)
#pragma unroll
        for (int nf=0;nf<8;++nf){
            int r=wm*32+mf*16+(lane>>2);
            int c=wn*64+nf*8+(lane&3)*2;
            float b0=b2b[c], b1v=b2b[c+1];
            float v00=fmaxf(acc[mf][nf][0]+b0,0.f), v01=fmaxf(acc[mf][nf][1]+b1v,0.f);
            float v10=fmaxf(acc[mf][nf][2]+b0,0.f), v11=fmaxf(acc[mf][nf][3]+b1v,0.f);
            __nv_bfloat16 h0,l0,h1,l1;
            splitf(v00,h0,l0); splitf(v01,h1,l1);
            __nv_bfloat162 hh,ll;
            hh.x=h0; hh.y=h1; ll.x=l0; ll.y=l1;
            *(__nv_bfloat162*)&AsH[r*S+c]=hh; *(__nv_bfloat162*)&AsL[r*S+c]=ll;
            splitf(v10,h0,l0); splitf(v11,h1,l1);
            hh.x=h0; hh.y=h1; ll.x=l0; ll.y=l1;
            *(__nv_bfloat162*)&AsH[(r+8)*S+c]=hh; *(__nv_bfloat162*)&AsL[(r+8)*S+c]=ll;
        }

    const int cv0=cnt[cg0], cv1=cnt[cg0+1];
    // ---- L3: K=128, N=256 in two halves ----
#pragma unroll
    for (int half=0; half<2; ++half){
        __syncthreads();   // prior mma done reading Ws / colmax consumed
        for (int t=tid; t<16384; t+=256){
            int n=t>>7,k=t&127;
            WsH[n*S+k]=wch[half*16384+t]; WsL[n*S+k]=wcl[half*16384+t];
        }
        __syncthreads();
#pragma unroll
        for (int mf=0;mf<2;++mf)
#pragma unroll
            for (int nf=0;nf<8;++nf)
#pragma unroll
                for (int q=0;q<4;++q) acc[mf][nf][q]=0.f;
        mma_block<8,8,S>(acc, AsH, AsL, WsH, WsL, wm, wn*64, lane);
#pragma unroll
        for (int nf=0;nf<8;++nf){
            int c=wn*64+nf*8+(lane&3)*2;
            float b0=b2c[half*128+c], b1v=b2c[half*128+c+1];
            float m0=-FLT_MAX, m1=-FLT_MAX;
#pragma unroll
            for (int mf=0;mf<2;++mf){
                int r=wm*32+mf*16+(lane>>2);
                int cv=(r>>6)?cv1:cv0;
                int rl=r&63;
                if (rl   < cv){ m0=fmaxf(m0,acc[mf][nf][0]+b0); m1=fmaxf(m1,acc[mf][nf][1]+b1v); }
                if (rl+8 < cv){ m0=fmaxf(m0,acc[mf][nf][2]+b0); m1=fmaxf(m1,acc[mf][nf][3]+b1v); }
            }
#pragma unroll
            for (int off=4; off<32; off<<=1){
                m0=fmaxf(m0,__shfl_xor_sync(0xffffffffu,m0,off));
                m1=fmaxf(m1,__shfl_xor_sync(0xffffffffu,m1,off));
            }
            if (lane<4){ colmax[wid*128+c]=m0; colmax[wid*128+c+1]=m1; }
        }
        __syncthreads();
        {
            int cent=tid>>7, col=tid&127;
            int wb=(col>>6)*4 + cent*2;
            float m=fmaxf(colmax[wb*128+col], colmax[(wb+1)*128+col]);
            int cv = cent? cv1:cv0;
            x2[(size_t)(cg0+cent)*256 + half*128 + col] = cv? m : 0.f;
        }
    }
}

// ---- fp32 GEMM (y1 + SA3): 128xTN tile, double-buffered ----
template<int TN>
__global__ void __launch_bounds__(256) gemm128_kernel(
    const float* __restrict__ A, const float* __restrict__ W,
    const float* __restrict__ bias, float* __restrict__ C,
    int N, int Kc, int relu)
{
    constexpr int JN = TN/16;
    constexpr int WL = (TN*16)/256;
    __shared__ float As[2][16*128];
    __shared__ float Ws[2][16*TN];
    const int tid = threadIdx.x;
    const int tx = tid & 15, ty = tid >> 4;
    const int bm = blockIdx.y*128, bn = blockIdx.x*TN;
    const int arow = tid >> 1, akk = (tid & 1)*8;
    const int nkt = (Kc + 15) >> 4;

    float acc[8][JN];
#pragma unroll
    for (int i=0;i<8;++i)
#pragma unroll
        for (int j=0;j<JN;++j) acc[i][j]=0.f;

#pragma unroll
    for (int j = 0; j < 8; ++j) {
        int k = akk + j;
        As[0][k*128 + arow] = (k < Kc) ? A[(size_t)(bm+arow)*Kc + k] : 0.f;
    }
#pragma unroll
    for (int r = 0; r < WL; ++r) {
        int e = tid + r*256;
        int n = e % TN, k = e / TN;
        Ws[0][k*TN + n] = (k < Kc) ? W[(size_t)k*N + bn + n] : 0.f;
    }
    __syncthreads();

    for (int kt = 0; kt < nkt; ++kt) {
        const int cur = kt & 1;
        float ra[8], rw[WL];
        if (kt+1 < nkt) {
            const int k0 = (kt+1) << 4;
#pragma unroll
            for (int j = 0; j < 8; ++j) {
                int k = k0 + akk + j;
                ra[j] = (k < Kc) ? A[(size_t)(bm+arow)*Kc + k] : 0.f;
            }
#pragma unroll
            for (int r = 0; r < WL; ++r) {
                int e = tid + r*256;
                int n = e % TN, k = k0 + e/TN;
                rw[r] = (k < Kc) ? W[(size_t)k*N + bn + n] : 0.f;
            }
        }
#pragma unroll
        for (int k = 0; k < 16; ++k) {
            float4 a0 = *(const float4*)&As[cur][k*128 + ty*4];
            float4 a1 = *(const float4*)&As[cur][k*128 + ty*4 + 64];
            float av[8] = {a0.x,a0.y,a0.z,a0.w,a1.x,a1.y,a1.z,a1.w};
            float bv[JN];
            float4 b0 = *(const float4*)&Ws[cur][k*TN + tx*4];
            bv[0]=b0.x; bv[1]=b0.y; bv[2]=b0.z; bv[3]=b0.w;
            if (TN == 128) {
                float4 b1 = *(const float4*)&Ws[cur][k*TN + tx*4 + 64];
                bv[4]=b1.x; bv[5]=b1.y; bv[6]=b1.z; bv[7]=b1.w;
            }
#pragma unroll
            for (int i=0;i<8;++i)
#pragma unroll
                for (int j=0;j<JN;++j) acc[i][j] += av[i]*bv[j];
        }
        if (kt+1 < nkt) {
#pragma unroll
            for (int j = 0; j < 8; ++j) As[cur^1][(akk+j)*128 + arow] = ra[j];
#pragma unroll
            for (int r = 0; r < WL; ++r) {
                int e = tid + r*256;
                Ws[cur^1][(e/TN)*TN + (e%TN)] = rw[r];
            }
            __syncthreads();
        }
    }

    float bb[JN];
#pragma unroll
    for (int j = 0; j < 4; ++j) bb[j] = bias[bn + tx*4 + j];
    if (TN == 128)
#pragma unroll
        for (int j = 4; j < 8; ++j) bb[j] = bias[bn + tx*4 + 64 + j-4];
#pragma unroll
    for (int i = 0; i < 8; ++i) {
        int row = bm + ((i<4) ? ty*4+i : ty*4+i-4+64);
        float v[JN];
#pragma unroll
        for (int j = 0; j < JN; ++j) {
            v[j] = acc[i][j] + bb[j];
            if (relu) v[j] = fmaxf(v[j], 0.f);
        }
        *(float4*)&C[(size_t)row*N + bn + tx*4] = make_float4(v[0],v[1],v[2],v[3]);
        if (TN == 128)
            *(float4*)&C[(size_t)row*N + bn + tx*4 + 64] = make_float4(v[4],v[5],v[6],v[7]);
    }
}

__global__ void feats3_kernel(const float* __restrict__ x2, const float* __restrict__ pos2,
                              float* __restrict__ feats)
{
    int row = blockIdx.x*4 + (threadIdx.x>>5), lane = threadIdx.x&31;
    const float* xs = x2 + (size_t)row*256;
    float* f = feats + (size_t)row*259;
    for (int i = lane; i < 256; i += 32) f[i]=xs[i];
    if (lane < 3) f[256+lane]=pos2[row*3+lane];
}

__global__ void pool256_kernel(const float* __restrict__ g, float* __restrict__ gfeat)
{
    int b = blockIdx.y, f = blockIdx.x*256 + threadIdx.x;
    float m = -FLT_MAX;
    for (int r = 0; r < M2C; ++r)
        m = fmaxf(m, g[(size_t)(b*M2C+r)*1024 + f]);
    gfeat[b*1024+f]=m;
}

__global__ void head_kernel(const float* __restrict__ gfeat,
                            const float* __restrict__ Wh1, const float* __restrict__ bh1,
                            const float* __restrict__ Wh2, const float* __restrict__ bh2,
                            const float* __restrict__ Wh3, const float* __restrict__ bh3,
                            float* __restrict__ out)
{
    __shared__ float gf[1024], h1[512], h2[256], lg[10];
    const int b=blockIdx.x, tid=threadIdx.x;
    for (int i = tid; i < 1024; i += 256) gf[i]=gfeat[b*1024+i];
    __syncthreads();
    for (int n = tid; n < 512; n += 256) {
        float s = bh1[n];
        for (int k = 0; k < 1024; ++k) s += gf[k]*Wh1[(size_t)k*512+n];
        h1[n]=fmaxf(s,0.f);
    }
    __syncthreads();
    { float s = bh2[tid];
      for (int k = 0; k < 512; ++k) s += h1[k]*Wh2[(size_t)k*256+tid];
      h2[tid]=fmaxf(s,0.f); }
    __syncthreads();
    if (tid < 10) {
        float s = bh3[tid];
        for (int k = 0; k < 256; ++k) s += h2[k]*Wh3[k*10+tid];
        lg[tid]=s;
    }
    __syncthreads();
    if (tid == 0) {
        float m=lg[0];
        for (int j=1;j<10;++j) m=fmaxf(m,lg[j]);
        float se=0.f;
        for (int j=0;j<10;++j) se+=expf(lg[j]-m);
        float l=logf(se);
        for (int j=0;j<10;++j) out[b*10+j]=lg[j]-m-l;
    }
}

extern "C" void kernel_launch(void* const* d_in, const int* in_sizes, int n_in,
                              void* d_out, int out_size)
{
    const float* pos=(const float*)d_in[0];
    const float *W1a=(const float*)d_in[1],  *b1a=(const float*)d_in[2];
    const float *W1b=(const float*)d_in[3],  *b1b=(const float*)d_in[4];
    const float *W1c=(const float*)d_in[5],  *b1c=(const float*)d_in[6];
    const float *W2a=(const float*)d_in[7],  *b2a=(const float*)d_in[8];
    const float *W2b=(const float*)d_in[9],  *b2b=(const float*)d_in[10];
    const float *W2c=(const float*)d_in[11], *b2c=(const float*)d_in[12];
    const float *W3a=(const float*)d_in[13], *b3a=(const float*)d_in[14];
    const float *W3b=(const float*)d_in[15], *b3b=(const float*)d_in[16];
    const float *W3c=(const float*)d_in[17], *b3c=(const float*)d_in[18];
    const float *Wh1=(const float*)d_in[19], *bh1=(const float*)d_in[20];
    const float *Wh2=(const float*)d_in[21], *bh2=(const float*)d_in[22];
    const float *Wh3=(const float*)d_in[23], *bh3=(const float*)d_in[24];

    float *curv,*pos1,*curv1,*pos2,*x1,*x2,*gfeat,*fF,*bA,*bB;
    int *fps1,*fps2,*nidx1,*cnt1,*nidx2,*cnt2;
    __nv_bfloat16 *w1bh,*w1bl,*w1ch,*w1cl,*w2bh,*w2bl,*w2ch,*w2cl;
    cudaGetSymbolAddress((void**)&curv, g_curv);
    cudaGetSymbolAddress((void**)&fps1, g_fps1);
    cudaGetSymbolAddress((void**)&fps2, g_fps2);
    cudaGetSymbolAddress((void**)&pos1, g_pos1);
    cudaGetSymbolAddress((void**)&curv1,g_curv1);
    cudaGetSymbolAddress((void**)&pos2, g_pos2);
    cudaGetSymbolAddress((void**)&nidx1,g_nidx1);
    cudaGetSymbolAddress((void**)&cnt1, g_cnt1);
    cudaGetSymbolAddress((void**)&nidx2,g_nidx2);
    cudaGetSymbolAddress((void**)&cnt2, g_cnt2);
    cudaGetSymbolAddress((void**)&x1,   g_x1);
    cudaGetSymbolAddress((void**)&x2,   g_x2);
    cudaGetSymbolAddress((void**)&gfeat,g_gfeat);
    cudaGetSymbolAddress((void**)&fF,   g_featF);
    cudaGetSymbolAddress((void**)&bA,   g_bufA);
    cudaGetSymbolAddress((void**)&bB,   g_bufB);
    cudaGetSymbolAddress((void**)&w1bh, g_w1bh); cudaGetSymbolAddress((void**)&w1bl, g_w1bl);
    cudaGetSymbolAddress((void**)&w1ch, g_w1ch); cudaGetSymbolAddress((void**)&w1cl, g_w1cl);
    cudaGetSymbolAddress((void**)&w2bh, g_w2bh); cudaGetSymbolAddress((void**)&w2bl, g_w2bl);
    cudaGetSymbolAddress((void**)&w2ch, g_w2ch); cudaGetSymbolAddress((void**)&w2cl, g_w2cl);

    cudaFuncSetAttribute(sa1_fused_kernel, cudaFuncAttributeMaxDynamicSharedMemorySize, 97280);
    cudaFuncSetAttribute(sa2_fused_kernel, cudaFuncAttributeMaxDynamicSharedMemorySize, 144896);

    // weight prep (first, so ncu -s captures the pipeline kernels)
    wprep_kernel<<<16, 256>>>(W1b, w1bh, w1bl, 64, 64);
    wprep_kernel<<<32, 256>>>(W1c, w1ch, w1cl, 64, 128);
    wprep_kernel<<<64, 256>>>(W2b, w2bh, w2bl, 128, 128);
    wprep_kernel<<<128,256>>>(W2c, w2ch, w2cl, 128, 256);

    // curvature + FPS level 1
    curvature_kernel<<<BATCH*(NPT/128), 128>>>(pos, curv);
    fps_kernel<NPT,M1C><<<BATCH, 256>>>(pos, curv, fps1);
    gather_kernel<<<(BATCH*M1C+255)/256, 256>>>(pos, curv, fps1, pos1, curv1, NPT, M1C, BATCH*M1C);

    // SA1
    group_kernel<NPT,128,8><<<dim3(M1C/8, BATCH), 256>>>(pos, pos1, nidx1, cnt1, M1C, 0.04f);
    sa1_fused_kernel<<<BATCH*M1C/2, 256, 97280>>>(pos, pos1, nidx1, cnt1,
        W1a, b1a, w1bh, w1bl, b1b, w1ch, w1cl, b1c, x1);

    // FPS level 2
    fps_kernel<M1C,M2C><<<BATCH, 256>>>(pos1, curv1, fps2);
    gather_kernel<<<(BATCH*M2C+255)/256, 256>>>(pos1, curv1, fps2, pos2, (float*)0, M1C, M2C, BATCH*M2C);

    // SA2
    group_kernel<M1C,512,4><<<dim3(M2C/4, BATCH), 128>>>(pos1, pos2, nidx2, cnt2, M2C, 0.16f);
    gemm128_kernel<128><<<dim3(1, BATCH*M1C/128), 256>>>(x1, W2a, b2a, fF, 128, 128, 0);  // y1
    sa2_fused_kernel<<<BATCH*M2C/2, 256, 144896>>>(fF, pos1, pos2, nidx2, cnt2,
        W2a, w2bh, w2bl, b2b, w2ch, w2cl, b2c, x2);

    // SA3 global
    {
        const int rows = BATCH*M2C;  // 2048
        feats3_kernel<<<rows/4, 128>>>(x2, pos2, fF);
        gemm128_kernel<64><<<dim3(4,  rows/128), 256>>>(fF, W3a, b3a, bA, 256, 259, 1);
        gemm128_kernel<64><<<dim3(8,  rows/128), 256>>>(bA, W3b, b3b, bB, 512, 256, 1);
        gemm128_kernel<64><<<dim3(16, rows/128), 256>>>(bB, W3c, b3c, bA, 1024, 512, 0);
        pool256_kernel<<<dim3(4, BATCH), 256>>>(bA, gfeat);
    }

    // head
    head_kernel<<<BATCH, 256>>>(gfeat, Wh1, bh1, Wh2, bh2, Wh3, bh3, (float*)d_out);
}

// round 6
// speedup vs baseline: 2.8468x; 1.1158x over previous
#include <cuda_runtime.h>
#include <cuda_bf16.h>
#include <math.h>
#include <float.h>

#define BATCH 8
#define NPT   2048
#define M1C   1024
#define M2C   256
#define KNB   64
#define CURVK 10

// ---- scratch (device globals; no allocation) ----
__device__ float g_curv [BATCH*NPT];
__device__ int   g_fps1 [BATCH*M1C];
__device__ int   g_fps2 [BATCH*M2C];
__device__ float g_pos1 [BATCH*M1C*3];
__device__ float g_curv1[BATCH*M1C];
__device__ float g_pos2 [BATCH*M2C*3];
__device__ int   g_nidx1[BATCH*M1C*KNB];
__device__ int   g_cnt1 [BATCH*M1C];
__device__ int   g_nidx2[BATCH*M2C*KNB];
__device__ int   g_cnt2 [BATCH*M2C];
__device__ float g_x1   [BATCH*M1C*128];
__device__ float g_x2   [BATCH*M2C*256];
__device__ float g_gfeat[BATCH*1024];
__device__ float g_featF[1024*1024];          // y1 (8192x128)
__device__ float g_bufA [2*1024*1024];        // SA3 final fp32 (2048x1024)
__device__ __nv_bfloat16 g_w1bh[4096],  g_w1bl[4096];    // W1b  [64][64]
__device__ __nv_bfloat16 g_w1ch[8192],  g_w1cl[8192];    // W1c  [128][64]
__device__ __nv_bfloat16 g_w2bh[16384], g_w2bl[16384];   // W2b  [128][128]
__device__ __nv_bfloat16 g_w2ch[32768], g_w2cl[32768];   // W2c  [256][128]
__device__ __nv_bfloat16 g_w3ah[73728], g_w3al[73728];   // W3a  [256][288]
__device__ __nv_bfloat16 g_w3bh[131072],g_w3bl[131072];  // W3b  [512][256]
__device__ __nv_bfloat16 g_w3ch[524288],g_w3cl[524288];  // W3c  [1024][512]
__device__ __nv_bfloat16 g_pAh[589824], g_pAl[589824];   // feats3 2048x288
__device__ __nv_bfloat16 g_pBh[524288], g_pBl[524288];   // 2048x256
__device__ __nv_bfloat16 g_pCh[1048576],g_pCl[1048576];  // 2048x512

__device__ __forceinline__ void splitf(float v, __nv_bfloat16& h, __nv_bfloat16& l) {
    h = __float2bfloat16(v);
    l = __float2bfloat16(v - __bfloat162float(h));
}

__device__ __forceinline__ void mma16816(float* c, const unsigned* a, const unsigned* b) {
    asm volatile(
      "mma.sync.aligned.m16n8k16.row.col.f32.bf16.bf16.f32 "
      "{%0,%1,%2,%3}, {%4,%5,%6,%7}, {%8,%9}, {%0,%1,%2,%3};\n"
      : "+f"(c[0]), "+f"(c[1]), "+f"(c[2]), "+f"(c[3])
      : "r"(a[0]), "r"(a[1]), "r"(a[2]), "r"(a[3]), "r"(b[0]), "r"(b[1]));
}

// shared mma block: 128 rows x (NF*8 cols per warp-half), 3-product bf16 split
template<int NF,int K16,int S>
__device__ __forceinline__ void mma_block(
    float (&acc)[2][8][4],
    const __nv_bfloat16* AsH, const __nv_bfloat16* AsL,
    const __nv_bfloat16* WH,  const __nv_bfloat16* WL,
    int wm, int wnbase, int lane)
{
#pragma unroll
    for (int k16=0;k16<K16;++k16){
        const int kk=k16*16+(lane&3)*2;
        unsigned ah[2][4], al[2][4];
#pragma unroll
        for (int mf=0;mf<2;++mf){
            int r=wm*32+mf*16+(lane>>2);
            ah[mf][0]=*(const unsigned*)&AsH[r*S+kk];
            ah[mf][1]=*(const unsigned*)&AsH[(r+8)*S+kk];
            ah[mf][2]=*(const unsigned*)&AsH[r*S+kk+8];
            ah[mf][3]=*(const unsigned*)&AsH[(r+8)*S+kk+8];
            al[mf][0]=*(const unsigned*)&AsL[r*S+kk];
            al[mf][1]=*(const unsigned*)&AsL[(r+8)*S+kk];
            al[mf][2]=*(const unsigned*)&AsL[r*S+kk+8];
            al[mf][3]=*(const unsigned*)&AsL[(r+8)*S+kk+8];
        }
#pragma unroll
        for (int nf=0;nf<NF;++nf){
            int n=wnbase+nf*8+(lane>>2);
            unsigned bh[2]={*(const unsigned*)&WH[n*S+kk], *(const unsigned*)&WH[n*S+kk+8]};
            unsigned bl[2]={*(const unsigned*)&WL[n*S+kk], *(const unsigned*)&WL[n*S+kk+8]};
#pragma unroll
            for (int mf=0;mf<2;++mf){
                mma16816(acc[mf][nf], ah[mf], bh);
                mma16816(acc[mf][nf], ah[mf], bl);
                mma16816(acc[mf][nf], al[mf], bh);
            }
        }
    }
}

// ---- curvature: 10-NN covariance eigen ratio ----
__global__ void curvature_kernel(const float* __restrict__ pos, float* __restrict__ curv)
{
    __shared__ float px[NPT], py[NPT], pz[NPT], nr[NPT];
    const int b = blockIdx.x / (NPT/128);
    const int tid = threadIdx.x;
    const float* cp = pos + (size_t)b * NPT * 3;
    for (int i = tid; i < NPT; i += 128) {
        float x = cp[3*i], y = cp[3*i+1], z = cp[3*i+2];
        px[i]=x; py[i]=y; pz[i]=z; nr[i]=x*x+y*y+z*z;
    }
    __syncthreads();
    const int i = (blockIdx.x % (NPT/128)) * 128 + tid;
    const float qx=px[i], qy=py[i], qz=pz[i], nq=nr[i];

    float td[CURVK]; int ti[CURVK];
#pragma unroll
    for (int s = 0; s < CURVK; ++s) { td[s]=3.4e38f; ti[s]=0; }
    for (int j = 0; j < NPT; ++j) {
        float d2 = nq + nr[j] - 2.0f*(qx*px[j]+qy*py[j]+qz*pz[j]);
        if (d2 < td[CURVK-1]) {
            float cd=d2; int ci=j;
#pragma unroll
            for (int s = 0; s < CURVK; ++s)
                if (cd < td[s]) { float t=td[s]; td[s]=cd; cd=t; int u=ti[s]; ti[s]=ci; ci=u; }
        }
    }
    float mx=0,my=0,mz=0;
#pragma unroll
    for (int s = 0; s < CURVK; ++s) { mx+=px[ti[s]]; my+=py[ti[s]]; mz+=pz[ti[s]]; }
    mx/=CURVK; my/=CURVK; mz/=CURVK;
    double cxx=0,cxy=0,cxz=0,cyy=0,cyz=0,czz=0;
#pragma unroll
    for (int s = 0; s < CURVK; ++s) {
        float ax=px[ti[s]]-mx, ay=py[ti[s]]-my, az=pz[ti[s]]-mz;
        cxx+=(double)ax*ax; cxy+=(double)ax*ay; cxz+=(double)ax*az;
        cyy+=(double)ay*ay; cyz+=(double)ay*az; czz+=(double)az*az;
    }
    cxx/=CURVK; cxy/=CURVK; cxz/=CURVK; cyy/=CURVK; cyz/=CURVK; czz/=CURVK;
    double tr=cxx+cyy+czz;
    double p1=cxy*cxy+cxz*cxz+cyz*cyz;
    double q=tr/3.0;
    double p2=(cxx-q)*(cxx-q)+(cyy-q)*(cyy-q)+(czz-q)*(czz-q)+2.0*p1;
    double lmin;
    if (p2 < 1e-32) lmin = q;
    else {
        double p=sqrt(p2/6.0);
        double b00=(cxx-q)/p,b11=(cyy-q)/p,b22=(czz-q)/p,b01=cxy/p,b02=cxz/p,b12=cyz/p;
        double detB=b00*(b11*b22-b12*b12)-b01*(b01*b22-b12*b02)+b02*(b01*b12-b11*b02);
        double r=fmin(1.0,fmax(-1.0,detB*0.5));
        lmin=q+2.0*p*cos(acos(r)/3.0 + 2.0943951023931953);
    }
    curv[b*NPT+i]=(float)(lmin/(tr+1e-8));
}

// ---- weighted FPS: register-resident, redux argmax, 1 barrier/iter, smem seed ----
template<int NPTS,int MOUT>
__global__ void __launch_bounds__(256) fps_kernel(const float* __restrict__ pos,
                                                  const float* __restrict__ curv,
                                                  int* __restrict__ out_idx)
{
    constexpr int THR=256, E=NPTS/THR;
    __shared__ float spx[NPTS], spy[NPTS], spz[NPTS];
    __shared__ unsigned long long wkey[2][8];
    const int b=blockIdx.x, tid=threadIdx.x, lane=tid&31, wid=tid>>5;
    const float* cp = pos + (size_t)b*NPTS*3;
    float px[E],py[E],pz[E],ww[E],md[E];
#pragma unroll
    for (int e=0;e<E;++e){
        int i=tid+e*THR;
        float x=cp[3*i], y=cp[3*i+1], z=cp[3*i+2];
        px[e]=x; py[e]=y; pz[e]=z;
        spx[i]=x; spy[i]=y; spz[i]=z;
        ww[e]=1.0f+10.0f*curv[b*NPTS+i];
        md[e]=FLT_MAX;
    }
    if (tid==0) out_idx[b*MOUT]=0;
    __syncthreads();
    float sx=spx[0], sy=spy[0], sz=spz[0];
    for (int m=1;m<MOUT;++m){
        float bv=-1.f; int bi=0;
#pragma unroll
        for (int e=0;e<E;++e){
            int i=tid+e*THR;
            float dx=px[e]-sx, dy=py[e]-sy, dz=pz[e]-sz;
            float d=fminf(md[e], dx*dx+dy*dy+dz*dz);
            md[e]=d;
            float v=d*ww[e];
            if (v>bv){ bv=v; bi=i; }       // i strictly increasing per thread -> first max kept
        }
        unsigned hv=__float_as_uint(bv);   // bv >= 0 -> bit order == float order
        unsigned hm=__reduce_max_sync(0xffffffffu, hv);
        unsigned lm=__reduce_max_sync(0xffffffffu, (hv==hm)? ~(unsigned)bi : 0u);
        if (lane==0) wkey[m&1][wid]=((unsigned long long)hm<<32)|lm;
        __syncthreads();
        unsigned long long k2 = (lane<8)? wkey[m&1][lane] : 0ull;
        unsigned h2=(unsigned)(k2>>32), l2=(unsigned)k2;
        unsigned hm2=__reduce_max_sync(0xffffffffu, h2);
        unsigned lm2=__reduce_max_sync(0xffffffffu, (h2==hm2)? l2 : 0u);
        int s=(int)(~lm2);
        if (tid==0) out_idx[b*MOUT+m]=s;
        sx=spx[s]; sy=spy[s]; sz=spz[s];
    }
}

__global__ void gather_kernel(const float* __restrict__ pos, const float* __restrict__ curv,
                              const int* __restrict__ idx, float* __restrict__ opos,
                              float* __restrict__ ocurv, int npts, int mout, int total)
{
    int t = blockIdx.x*256 + threadIdx.x;
    if (t >= total) return;
    int b = t / mout, i = idx[t], src = b*npts + i;
    opos[3*t]=pos[3*src]; opos[3*t+1]=pos[3*src+1]; opos[3*t+2]=pos[3*src+2];
    if (ocurv) ocurv[t]=curv[src];
}

// ---- radius grouping ----
template<int NPTS,int CAP,int CPB>
__global__ void group_kernel(const float* __restrict__ pts, const float* __restrict__ cents,
                             int* __restrict__ nidx, int* __restrict__ cnt_out,
                             int MC, float r2)
{
    __shared__ float px[NPTS],py[NPTS],pz[NPTS],nr[NPTS];
    __shared__ unsigned long long cand[CPB][CAP];
    const int b=blockIdx.y, tid=threadIdx.x;
    const float* cp = pts + (size_t)b*NPTS*3;
    for (int i = tid; i < NPTS; i += CPB*32) {
        float x=cp[3*i],y=cp[3*i+1],z=cp[3*i+2];
        px[i]=x; py[i]=y; pz[i]=z; nr[i]=x*x+y*y+z*z;
    }
    __syncthreads();
    const int w=tid>>5, lane=tid&31;
    const int c=blockIdx.x*CPB+w, cg=b*MC+c;
    const float cx=cents[3*cg],cy=cents[3*cg+1],cz=cents[3*cg+2];
    const float nc=cx*cx+cy*cy+cz*cz;
    int cnt=0;
    for (int j0 = 0; j0 < NPTS; j0 += 32) {
        int j=j0+lane;
        float d2 = nc + nr[j] - 2.0f*(cx*px[j]+cy*py[j]+cz*pz[j]);
        bool in = (d2 <= r2);
        unsigned mask = __ballot_sync(0xffffffffu, in);
        if (in) {
            int p = cnt + __popc(mask & ((1u<<lane)-1u));
            if (p < CAP) {
                unsigned ub=__float_as_uint(d2);
                ub = (ub&0x80000000u) ? ~ub : (ub|0x80000000u);
                cand[w][p] = ((unsigned long long)ub<<32) | (unsigned)j;
            }
        }
        cnt += __popc(mask);
    }
    if (cnt > CAP) cnt = CAP;
    for (int i = cnt+lane; i < CAP; i += 32) cand[w][i]=0xFFFFFFFFFFFFFFFFull;
    __syncwarp();
    for (int k = 2; k <= CAP; k <<= 1)
        for (int j = k>>1; j > 0; j >>= 1) {
            for (int i = lane; i < CAP; i += 32) {
                int ixj = i^j;
                if (ixj > i) {
                    unsigned long long a=cand[w][i], bb=cand[w][ixj];
                    if ((a>bb) == ((i&k)==0)) { cand[w][i]=bb; cand[w][ixj]=a; }
                }
            }
            __syncwarp();
        }
    int nv = cnt < KNB ? cnt : KNB;
    int fb = (nv>0) ? (int)(cand[w][0]&0xffffffffu) : 0;
    for (int i = lane; i < KNB; i += 32)
        nidx[(size_t)cg*KNB+i] = (i<nv) ? (int)(cand[w][i]&0xffffffffu) : fb;
    if (lane==0) cnt_out[cg]=nv;
}

// ---- weight prep: W[K][N] fp32 -> transposed split planes [N][K] ----
__global__ void wprep_kernel(const float* __restrict__ W,
                             __nv_bfloat16* __restrict__ hi, __nv_bfloat16* __restrict__ lo,
                             int K, int N)
{
    int t = blockIdx.x*256 + threadIdx.x;
    if (t >= K*N) return;
    int n = t / K, k = t % K;
    __nv_bfloat16 h,l; splitf(W[(size_t)k*N + n], h, l);
    hi[t]=h; lo[t]=l;
}

// ---- weight prep with K zero-pad ----
__global__ void wprep_pad_kernel(const float* __restrict__ W,
                                 __nv_bfloat16* __restrict__ hi, __nv_bfloat16* __restrict__ lo,
                                 int K, int N, int Kpad)
{
    int t = blockIdx.x*256 + threadIdx.x;
    if (t >= N*Kpad) return;
    int n = t / Kpad, k = t % Kpad;
    float v = (k < K) ? W[(size_t)k*N + n] : 0.f;
    __nv_bfloat16 h,l; splitf(v, h, l);
    hi[t]=h; lo[t]=l;
}

// ---- fused SA1 (persistent): weights loaded once, grid-stride over tiles ----
__global__ void __launch_bounds__(256) sa1_fused_kernel(
    const float* __restrict__ pos, const float* __restrict__ pos1,
    const int* __restrict__ nidx, const int* __restrict__ cnt,
    const float* __restrict__ W1a, const float* __restrict__ b1a,
    const __nv_bfloat16* __restrict__ wbh, const __nv_bfloat16* __restrict__ wbl,
    const float* __restrict__ b1b,
    const __nv_bfloat16* __restrict__ wch, const __nv_bfloat16* __restrict__ wcl,
    const float* __restrict__ b1c,
    float* __restrict__ x1)
{
    constexpr int S = 72;   // K=64 + 8 pad
    extern __shared__ __align__(16) char sm1[];
    __nv_bfloat16* AsH = (__nv_bfloat16*)sm1;
    __nv_bfloat16* AsL = AsH + 128*S;
    __nv_bfloat16* WcH = AsL + 128*S;
    __nv_bfloat16* WcL = WcH + 128*S;
    __nv_bfloat16* WbH = WcL + 128*S;
    __nv_bfloat16* WbL = WbH + 64*S;
    float* w1s   = (float*)(WbL + 64*S);   // 192 W1a + 64 b1a
    float* colmax= w1s + 256;              // [8][128]

    const int tid=threadIdx.x, lane=tid&31, wid=tid>>5;
    const int wm=wid&3, wn=wid>>2;

    for (int t=tid; t<64*64;  t+=256){ int n=t>>6,k=t&63; WbH[n*S+k]=wbh[t]; WbL[n*S+k]=wbl[t]; }
    for (int t=tid; t<128*64; t+=256){ int n=t>>6,k=t&63; WcH[n*S+k]=wch[t]; WcL[n*S+k]=wcl[t]; }
    if (tid<192) w1s[tid]=W1a[tid];
    else if (tid<256) w1s[tid]=b1a[tid-192];

    const int NT = BATCH*M1C/2;
    for (int tile = blockIdx.x; tile < NT; tile += gridDim.x) {
        const int cg0 = tile*2;
        __syncthreads();
        // L1 build (scalar): 128 rows x 64
        {
            const int row=tid>>1, h0=(tid&1)*32;
            const int cg = cg0 + (row>>6);
            const int p  = nidx[cg*64 + (row&63)];
            const int src = (cg>>10)*NPT + p;
            const float rx = pos[3*src]  -pos1[3*cg];
            const float ry = pos[3*src+1]-pos1[3*cg+1];
            const float rz = pos[3*src+2]-pos1[3*cg+2];
#pragma unroll
            for (int j=0;j<32;++j){
                int n=h0+j;
                float v=fmaxf(rx*w1s[n]+ry*w1s[64+n]+rz*w1s[128+n]+w1s[192+n],0.f);
                splitf(v, AsH[row*S+n], AsL[row*S+n]);
            }
        }
        __syncthreads();

        float acc[2][8][4];
        // ---- L2: K=64, N=64 ----
#pragma unroll
        for (int mf=0;mf<2;++mf)
#pragma unroll
            for (int nf=0;nf<4;++nf)
#pragma unroll
                for (int q=0;q<4;++q) acc[mf][nf][q]=0.f;
        mma_block<4,4,S>(acc, AsH, AsL, WbH, WbL, wm, wn*32, lane);
        __syncthreads();
#pragma unroll
        for (int mf=0;mf<2;++mf)
#pragma unroll
            for (int nf=0;nf<4;++nf){
                int r=wm*32+mf*16+(lane>>2);
                int c=wn*32+nf*8+(lane&3)*2;
                float b0=b1b[c], b1v=b1b[c+1];
                float v00=fmaxf(acc[mf][nf][0]+b0,0.f), v01=fmaxf(acc[mf][nf][1]+b1v,0.f);
                float v10=fmaxf(acc[mf][nf][2]+b0,0.f), v11=fmaxf(acc[mf][nf][3]+b1v,0.f);
                __nv_bfloat16 h0,l0,h1,l1;
                splitf(v00,h0,l0); splitf(v01,h1,l1);
                __nv_bfloat162 hh,ll;
                hh.x=h0; hh.y=h1; ll.x=l0; ll.y=l1;
                *(__nv_bfloat162*)&AsH[r*S+c]=hh; *(__nv_bfloat162*)&AsL[r*S+c]=ll;
                splitf(v10,h0,l0); splitf(v11,h1,l1);
                hh.x=h0; hh.y=h1; ll.x=l0; ll.y=l1;
                *(__nv_bfloat162*)&AsH[(r+8)*S+c]=hh; *(__nv_bfloat162*)&AsL[(r+8)*S+c]=ll;
            }
        __syncthreads();

        // ---- L3: K=64, N=128 ----
#pragma unroll
        for (int mf=0;mf<2;++mf)
#pragma unroll
            for (int nf=0;nf<8;++nf)
#pragma unroll
                for (int q=0;q<4;++q) acc[mf][nf][q]=0.f;
        mma_block<8,4,S>(acc, AsH, AsL, WcH, WcL, wm, wn*64, lane);

        const int cv0=cnt[cg0], cv1=cnt[cg0+1];
#pragma unroll
        for (int nf=0;nf<8;++nf){
            int c=wn*64+nf*8+(lane&3)*2;
            float b0=b1c[c], b1v=b1c[c+1];
            float m0=-FLT_MAX, m1=-FLT_MAX;
#pragma unroll
            for (int mf=0;mf<2;++mf){
                int r=wm*32+mf*16+(lane>>2);
                int cv=(r>>6)?cv1:cv0;
                int rl=r&63;
                if (rl   < cv){ m0=fmaxf(m0,acc[mf][nf][0]+b0); m1=fmaxf(m1,acc[mf][nf][1]+b1v); }
                if (rl+8 < cv){ m0=fmaxf(m0,acc[mf][nf][2]+b0); m1=fmaxf(m1,acc[mf][nf][3]+b1v); }
            }
#pragma unroll
            for (int off=4; off<32; off<<=1){
                m0=fmaxf(m0,__shfl_xor_sync(0xffffffffu,m0,off));
                m1=fmaxf(m1,__shfl_xor_sync(0xffffffffu,m1,off));
            }
            if (lane<4){ colmax[wid*128+c]=m0; colmax[wid*128+c+1]=m1; }
        }
        __syncthreads();
        {
            int cent=tid>>7, col=tid&127;
            int wb=(col>>6)*4 + cent*2;
            float m=fmaxf(colmax[wb*128+col], colmax[(wb+1)*128+col]);
            int cv = cent? cv1:cv0;
            x1[(size_t)(cg0+cent)*128+col] = cv? m : 0.f;
        }
    }
}

// ---- fused SA2: 2 centroids/block ----
__global__ void __launch_bounds__(256) sa2_fused_kernel(
    const float* __restrict__ y1, const float* __restrict__ pos1,
    const float* __restrict__ pos2, const int* __restrict__ nidx,
    const int* __restrict__ cnt, const float* __restrict__ W2a,
    const __nv_bfloat16* __restrict__ wbh, const __nv_bfloat16* __restrict__ wbl,
    const float* __restrict__ b2b,
    const __nv_bfloat16* __restrict__ wch, const __nv_bfloat16* __restrict__ wcl,
    const float* __restrict__ b2c,
    float* __restrict__ x2)
{
    constexpr int S = 136;  // K=128 + 8 pad
    extern __shared__ __align__(16) char sm2[];
    __nv_bfloat16* AsH = (__nv_bfloat16*)sm2;
    __nv_bfloat16* AsL = AsH + 128*S;
    __nv_bfloat16* WsH = AsL + 128*S;
    __nv_bfloat16* WsL = WsH + 128*S;
    float* w2a3  = (float*)(WsL + 128*S);  // 384
    float* colmax= w2a3 + 384;             // [8][128]

    const int tid=threadIdx.x, lane=tid&31, wid=tid>>5;
    const int wm=wid&3, wn=wid>>2;
    const int cg0 = blockIdx.x*2;

    for (int t=tid; t<384; t+=256) w2a3[t]=W2a[16384+t];
    for (int t=tid; t<16384; t+=256){ int n=t>>7,k=t&127; WsH[n*S+k]=wbh[t]; WsL[n*S+k]=wbl[t]; }
    __syncthreads();

    {
        const int row=tid>>1, h0=(tid&1)*64;
        const int cg = cg0 + (row>>6);
        const int gp = (cg>>8)*M1C + nidx[cg*64 + (row&63)];
        const float rx = pos1[3*gp]  -pos2[3*cg];
        const float ry = pos1[3*gp+1]-pos2[3*cg+1];
        const float rz = pos1[3*gp+2]-pos2[3*cg+2];
        const float* yr = y1 + (size_t)gp*128;
#pragma unroll
        for (int j=0;j<64;++j){
            int n=h0+j;
            float v=fmaxf(yr[n]+rx*w2a3[n]+ry*w2a3[128+n]+rz*w2a3[256+n],0.f);
            splitf(v, AsH[row*S+n], AsL[row*S+n]);
        }
    }
    __syncthreads();

    float acc[2][8][4];
#pragma unroll
    for (int mf=0;mf<2;++mf)
#pragma unroll
        for (int nf=0;nf<8;++nf)
#pragma unroll
            for (int q=0;q<4;++q) acc[mf][nf][q]=0.f;
    mma_block<8,8,S>(acc, AsH, AsL, WsH, WsL, wm, wn*64, lane);
    __syncthreads();
#pragma unroll
    for (int mf=0;mf<2;++mf)
#pragma unroll
        for (int nf=0;nf<8;++nf){
            int r=wm*32+mf*16+(lane>>2);
            int c=wn*64+nf*8+(lane&3)*2;
            float b0=b2b[c], b1v=b2b[c+1];
            float v00=fmaxf(acc[mf][nf][0]+b0,0.f), v01=fmaxf(acc[mf][nf][1]+b1v,0.f);
            float v10=fmaxf(acc[mf][nf][2]+b0,0.f), v11=fmaxf(acc[mf][nf][3]+b1v,0.f);
            __nv_bfloat16 h0,l0,h1,l1;
            splitf(v00,h0,l0); splitf(v01,h1,l1);
            __nv_bfloat162 hh,ll;
            hh.x=h0; hh.y=h1; ll.x=l0; ll.y=l1;
            *(__nv_bfloat162*)&AsH[r*S+c]=hh; *(__nv_bfloat162*)&AsL[r*S+c]=ll;
            splitf(v10,h0,l0); splitf(v11,h1,l1);
            hh.x=h0; hh.y=h1; ll.x=l0; ll.y=l1;
            *(__nv_bfloat162*)&AsH[(r+8)*S+c]=hh; *(__nv_bfloat162*)&AsL[(r+8)*S+c]=ll;
        }

    const int cv0=cnt[cg0], cv1=cnt[cg0+1];
#pragma unroll
    for (int half=0; half<2; ++half){
        __syncthreads();
        for (int t=tid; t<16384; t+=256){
            int n=t>>7,k=t&127;
            WsH[n*S+k]=wch[half*16384+t]; WsL[n*S+k]=wcl[half*16384+t];
        }
        __syncthreads();
#pragma unroll
        for (int mf=0;mf<2;++mf)
#pragma unroll
            for (int nf=0;nf<8;++nf)
#pragma unroll
                for (int q=0;q<4;++q) acc[mf][nf][q]=0.f;
        mma_block<8,8,S>(acc, AsH, AsL, WsH, WsL, wm, wn*64, lane);
#pragma unroll
        for (int nf=0;nf<8;++nf){
            int c=wn*64+nf*8+(lane&3)*2;
            float b0=b2c[half*128+c], b1v=b2c[half*128+c+1];
            float m0=-FLT_MAX, m1=-FLT_MAX;
#pragma unroll
            for (int mf=0;mf<2;++mf){
                int r=wm*32+mf*16+(lane>>2);
                int cv=(r>>6)?cv1:cv0;
                int rl=r&63;
                if (rl   < cv){ m0=fmaxf(m0,acc[mf][nf][0]+b0); m1=fmaxf(m1,acc[mf][nf][1]+b1v); }
                if (rl+8 < cv){ m0=fmaxf(m0,acc[mf][nf][2]+b0); m1=fmaxf(m1,acc[mf][nf][3]+b1v); }
            }
#pragma unroll
            for (int off=4; off<32; off<<=1){
                m0=fmaxf(m0,__shfl_xor_sync(0xffffffffu,m0,off));
                m1=fmaxf(m1,__shfl_xor_sync(0xffffffffu,m1,off));
            }
            if (lane<4){ colmax[wid*128+c]=m0; colmax[wid*128+c+1]=m1; }
        }
        __syncthreads();
        {
            int cent=tid>>7, col=tid&127;
            int wb=(col>>6)*4 + cent*2;
            float m=fmaxf(colmax[wb*128+col], colmax[(wb+1)*128+col]);
            int cv = cent? cv1:cv0;
            x2[(size_t)(cg0+cent)*256 + half*128 + col] = cv? m : 0.f;
        }
    }
}

// ---- generic tensor-core GEMM (round-4, passed): 128x64 tile, split bf16 ----
__global__ void __launch_bounds__(256) mma_gemm_kernel(
    const __nv_bfloat16* __restrict__ Ahi, const __nv_bfloat16* __restrict__ Alo,
    const __nv_bfloat16* __restrict__ Whi, const __nv_bfloat16* __restrict__ Wlo,
    const float* __restrict__ bias,
    float* __restrict__ outF,
    __nv_bfloat16* __restrict__ outHi, __nv_bfloat16* __restrict__ outLo,
    int N, int K, int relu)
{
    __shared__ __nv_bfloat16 AsH[128][34], AsL[128][34], WsH[64][34], WsL[64][34];
    const int tid = threadIdx.x;
    const int lane = tid & 31, wid = tid >> 5;
    const int wm = wid & 3, wn = wid >> 2;
    const int bm = blockIdx.y*128, bn = blockIdx.x*64;
    const int tcol = (tid & 15)*2, trow = tid >> 4;

    float acc[2][4][4];
#pragma unroll
    for (int mf=0; mf<2; ++mf)
#pragma unroll
        for (int nf=0; nf<4; ++nf)
#pragma unroll
            for (int q=0; q<4; ++q) acc[mf][nf][q]=0.f;

    for (int k0 = 0; k0 < K; k0 += 32) {
#pragma unroll
        for (int p = 0; p < 8; ++p) {
            int r = trow + p*16;
            size_t ga = (size_t)(bm + r)*K + k0 + tcol;
            *(unsigned*)&AsH[r][tcol] = *(const unsigned*)&Ahi[ga];
            *(unsigned*)&AsL[r][tcol] = *(const unsigned*)&Alo[ga];
        }
#pragma unroll
        for (int p = 0; p < 4; ++p) {
            int n = trow + p*16;
            size_t gw = (size_t)(bn + n)*K + k0 + tcol;
            *(unsigned*)&WsH[n][tcol] = *(const unsigned*)&Whi[gw];
            *(unsigned*)&WsL[n][tcol] = *(const unsigned*)&Wlo[gw];
        }
        __syncthreads();
#pragma unroll
        for (int ks = 0; ks < 2; ++ks) {
            const int kk = ks*16 + (lane&3)*2;
            unsigned ah[2][4], al[2][4], bh[4][2], bl[4][2];
#pragma unroll
            for (int mf=0; mf<2; ++mf) {
                int r = wm*32 + mf*16 + (lane>>2);
                ah[mf][0]=*(const unsigned*)&AsH[r][kk];
                ah[mf][1]=*(const unsigned*)&AsH[r+8][kk];
                ah[mf][2]=*(const unsigned*)&AsH[r][kk+8];
                ah[mf][3]=*(const unsigned*)&AsH[r+8][kk+8];
                al[mf][0]=*(const unsigned*)&AsL[r][kk];
                al[mf][1]=*(const unsigned*)&AsL[r+8][kk];
                al[mf][2]=*(const unsigned*)&AsL[r][kk+8];
                al[mf][3]=*(const unsigned*)&AsL[r+8][kk+8];
            }
#pragma unroll
            for (int nf=0; nf<4; ++nf) {
                int n = wn*32 + nf*8 + (lane>>2);
                bh[nf][0]=*(const unsigned*)&WsH[n][kk];
                bh[nf][1]=*(const unsigned*)&WsH[n][kk+8];
                bl[nf][0]=*(const unsigned*)&WsL[n][kk];
                bl[nf][1]=*(const unsigned*)&WsL[n][kk+8];
            }
#pragma unroll
            for (int mf=0; mf<2; ++mf)
#pragma unroll
                for (int nf=0; nf<4; ++nf) {
                    mma16816(acc[mf][nf], ah[mf], bh[nf]);
                    mma16816(acc[mf][nf], ah[mf], bl[nf]);
                    mma16816(acc[mf][nf], al[mf], bh[nf]);
                }
        }
        __syncthreads();
    }

#pragma unroll
    for (int mf=0; mf<2; ++mf)
#pragma unroll
        for (int nf=0; nf<4; ++nf) {
            int r = bm + wm*32 + mf*16 + (lane>>2);
            int c = bn + wn*32 + nf*8 + (lane&3)*2;
            float b0 = bias[c], b1 = bias[c+1];
            float v00 = acc[mf][nf][0]+b0, v01 = acc[mf][nf][1]+b1;
            float v10 = acc[mf][nf][2]+b0, v11 = acc[mf][nf][3]+b1;
            if (relu) {
                v00=fmaxf(v00,0.f); v01=fmaxf(v01,0.f);
                v10=fmaxf(v10,0.f); v11=fmaxf(v11,0.f);
            }
            if (outF) {
                outF[(size_t)r*N + c]   = v00; outF[(size_t)r*N + c+1]   = v01;
                outF[(size_t)(r+8)*N+c] = v10; outF[(size_t)(r+8)*N+c+1] = v11;
            }
            if (outHi) {
                __nv_bfloat16 h0,l0,h1,l1;
                splitf(v00,h0,l0); splitf(v01,h1,l1);
                __nv_bfloat162 hh; hh.x=h0; hh.y=h1;
                __nv_bfloat162 ll; ll.x=l0; ll.y=l1;
                *(__nv_bfloat162*)&outHi[(size_t)r*N + c] = hh;
                *(__nv_bfloat162*)&outLo[(size_t)r*N + c] = ll;
                splitf(v10,h0,l0); splitf(v11,h1,l1);
                hh.x=h0; hh.y=h1; ll.x=l0; ll.y=l1;
                *(__nv_bfloat162*)&outHi[(size_t)(r+8)*N + c] = hh;
                *(__nv_bfloat162*)&outLo[(size_t)(r+8)*N + c] = ll;
            }
        }
}

// ---- fp32 GEMM (y1): 128x128 tile, double-buffered ----
template<int TN>
__global__ void __launch_bounds__(256) gemm128_kernel(
    const float* __restrict__ A, const float* __restrict__ W,
    const float* __restrict__ bias, float* __restrict__ C,
    int N, int Kc, int relu)
{
    constexpr int JN = TN/16;
    constexpr int WL = (TN*16)/256;
    __shared__ float As[2][16*128];
    __shared__ float Ws[2][16*TN];
    const int tid = threadIdx.x;
    const int tx = tid & 15, ty = tid >> 4;
    const int bm = blockIdx.y*128, bn = blockIdx.x*TN;
    const int arow = tid >> 1, akk = (tid & 1)*8;
    const int nkt = (Kc + 15) >> 4;

    float acc[8][JN];
#pragma unroll
    for (int i=0;i<8;++i)
#pragma unroll
        for (int j=0;j<JN;++j) acc[i][j]=0.f;

#pragma unroll
    for (int j = 0; j < 8; ++j) {
        int k = akk + j;
        As[0][k*128 + arow] = (k < Kc) ? A[(size_t)(bm+arow)*Kc + k] : 0.f;
    }
#pragma unroll
    for (int r = 0; r < WL; ++r) {
        int e = tid + r*256;
        int n = e % TN, k = e / TN;
        Ws[0][k*TN + n] = (k < Kc) ? W[(size_t)k*N + bn + n] : 0.f;
    }
    __syncthreads();

    for (int kt = 0; kt < nkt; ++kt) {
        const int cur = kt & 1;
        float ra[8], rw[WL];
        if (kt+1 < nkt) {
            const int k0 = (kt+1) << 4;
#pragma unroll
            for (int j = 0; j < 8; ++j) {
                int k = k0 + akk + j;
                ra[j] = (k < Kc) ? A[(size_t)(bm+arow)*Kc + k] : 0.f;
            }
#pragma unroll
            for (int r = 0; r < WL; ++r) {
                int e = tid + r*256;
                int n = e % TN, k = k0 + e/TN;
                rw[r] = (k < Kc) ? W[(size_t)k*N + bn + n] : 0.f;
            }
        }
#pragma unroll
        for (int k = 0; k < 16; ++k) {
            float4 a0 = *(const float4*)&As[cur][k*128 + ty*4];
            float4 a1 = *(const float4*)&As[cur][k*128 + ty*4 + 64];
            float av[8] = {a0.x,a0.y,a0.z,a0.w,a1.x,a1.y,a1.z,a1.w};
            float bv[JN];
            float4 b0 = *(const float4*)&Ws[cur][k*TN + tx*4];
            bv[0]=b0.x; bv[1]=b0.y; bv[2]=b0.z; bv[3]=b0.w;
            if (TN == 128) {
                float4 b1 = *(const float4*)&Ws[cur][k*TN + tx*4 + 64];
                bv[4]=b1.x; bv[5]=b1.y; bv[6]=b1.z; bv[7]=b1.w;
            }
#pragma unroll
            for (int i=0;i<8;++i)
#pragma unroll
                for (int j=0;j<JN;++j) acc[i][j] += av[i]*bv[j];
        }
        if (kt+1 < nkt) {
#pragma unroll
            for (int j = 0; j < 8; ++j) As[cur^1][(akk+j)*128 + arow] = ra[j];
#pragma unroll
            for (int r = 0; r < WL; ++r) {
                int e = tid + r*256;
                Ws[cur^1][(e/TN)*TN + (e%TN)] = rw[r];
            }
            __syncthreads();
        }
    }

    float bb[JN];
#pragma unroll
    for (int j = 0; j < 4; ++j) bb[j] = bias[bn + tx*4 + j];
    if (TN == 128)
#pragma unroll
        for (int j = 4; j < 8; ++j) bb[j] = bias[bn + tx*4 + 64 + j-4];
#pragma unroll
    for (int i = 0; i < 8; ++i) {
        int row = bm + ((i<4) ? ty*4+i : ty*4+i-4+64);
        float v[JN];
#pragma unroll
        for (int j = 0; j < JN; ++j) {
            v[j] = acc[i][j] + bb[j];
            if (relu) v[j] = fmaxf(v[j], 0.f);
        }
        *(float4*)&C[(size_t)row*N + bn + tx*4] = make_float4(v[0],v[1],v[2],v[3]);
        if (TN == 128)
            *(float4*)&C[(size_t)row*N + bn + tx*4 + 64] = make_float4(v[4],v[5],v[6],v[7]);
    }
}

// ---- SA3 feature build with split + K-pad to 288 ----
__global__ void feats3_split_kernel(const float* __restrict__ x2, const float* __restrict__ pos2,
                                    __nv_bfloat16* __restrict__ hi, __nv_bfloat16* __restrict__ lo)
{
    int row = blockIdx.x*2 + (threadIdx.x>>7);
    int c0 = threadIdx.x & 127;
    for (int c = c0; c < 288; c += 128) {
        float v = (c < 256) ? x2[(size_t)row*256 + c]
                : (c < 259) ? pos2[row*3 + c - 256] : 0.f;
        splitf(v, hi[(size_t)row*288 + c], lo[(size_t)row*288 + c]);
    }
}

__global__ void pool256_kernel(const float* __restrict__ g, float* __restrict__ gfeat)
{
    int b = blockIdx.y, f = blockIdx.x*256 + threadIdx.x;
    float m = -FLT_MAX;
    for (int r = 0; r < M2C; ++r)
        m = fmaxf(m, g[(size_t)(b*M2C+r)*1024 + f]);
    gfeat[b*1024+f]=m;
}

__global__ void head_kernel(const float* __restrict__ gfeat,
                            const float* __restrict__ Wh1, const float* __restrict__ bh1,
                            const float* __restrict__ Wh2, const float* __restrict__ bh2,
                            const float* __restrict__ Wh3, const float* __restrict__ bh3,
                            float* __restrict__ out)
{
    __shared__ float gf[1024], h1[512], h2[256], lg[10];
    const int b=blockIdx.x, tid=threadIdx.x;
    for (int i = tid; i < 1024; i += 256) gf[i]=gfeat[b*1024+i];
    __syncthreads();
    for (int n = tid; n < 512; n += 256) {
        float s = bh1[n];
        for (int k = 0; k < 1024; ++k) s += gf[k]*Wh1[(size_t)k*512+n];
        h1[n]=fmaxf(s,0.f);
    }
    __syncthreads();
    { float s = bh2[tid];
      for (int k = 0; k < 512; ++k) s += h1[k]*Wh2[(size_t)k*256+tid];
      h2[tid]=fmaxf(s,0.f); }
    __syncthreads();
    if (tid < 10) {
        float s = bh3[tid];
        for (int k = 0; k < 256; ++k) s += h2[k]*Wh3[k*10+tid];
        lg[tid]=s;
    }
    __syncthreads();
    if (tid == 0) {
        float m=lg[0];
        for (int j=1;j<10;++j) m=fmaxf(m,lg[j]);
        float se=0.f;
        for (int j=0;j<10;++j) se+=expf(lg[j]-m);
        float l=logf(se);
        for (int j=0;j<10;++j) out[b*10+j]=lg[j]-m-l;
    }
}

extern "C" void kernel_launch(void* const* d_in, const int* in_sizes, int n_in,
                              void* d_out, int out_size)
{
    const float* pos=(const float*)d_in[0];
    const float *W1a=(const float*)d_in[1],  *b1a=(const float*)d_in[2];
    const float *W1b=(const float*)d_in[3],  *b1b=(const float*)d_in[4];
    const float *W1c=(const float*)d_in[5],  *b1c=(const float*)d_in[6];
    const float *W2a=(const float*)d_in[7],  *b2a=(const float*)d_in[8];
    const float *W2b=(const float*)d_in[9],  *b2b=(const float*)d_in[10];
    const float *W2c=(const float*)d_in[11], *b2c=(const float*)d_in[12];
    const float *W3a=(const float*)d_in[13], *b3a=(const float*)d_in[14];
    const float *W3b=(const float*)d_in[15], *b3b=(const float*)d_in[16];
    const float *W3c=(const float*)d_in[17], *b3c=(const float*)d_in[18];
    const float *Wh1=(const float*)d_in[19], *bh1=(const float*)d_in[20];
    const float *Wh2=(const float*)d_in[21], *bh2=(const float*)d_in[22];
    const float *Wh3=(const float*)d_in[23], *bh3=(const float*)d_in[24];

    float *curv,*pos1,*curv1,*pos2,*x1,*x2,*gfeat,*fF,*bA;
    int *fps1,*fps2,*nidx1,*cnt1,*nidx2,*cnt2;
    __nv_bfloat16 *w1bh,*w1bl,*w1ch,*w1cl,*w2bh,*w2bl,*w2ch,*w2cl;
    __nv_bfloat16 *w3ah,*w3al,*w3bh,*w3bl,*w3ch,*w3cl;
    __nv_bfloat16 *pAh,*pAl,*pBh,*pBl,*pCh,*pCl;
    cudaGetSymbolAddress((void**)&curv, g_curv);
    cudaGetSymbolAddress((void**)&fps1, g_fps1);
    cudaGetSymbolAddress((void**)&fps2, g_fps2);
    cudaGetSymbolAddress((void**)&pos1, g_pos1);
    cudaGetSymbolAddress((void**)&curv1,g_curv1);
    cudaGetSymbolAddress((void**)&pos2, g_pos2);
    cudaGetSymbolAddress((void**)&nidx1,g_nidx1);
    cudaGetSymbolAddress((void**)&cnt1, g_cnt1);
    cudaGetSymbolAddress((void**)&nidx2,g_nidx2);
    cudaGetSymbolAddress((void**)&cnt2, g_cnt2);
    cudaGetSymbolAddress((void**)&x1,   g_x1);
    cudaGetSymbolAddress((void**)&x2,   g_x2);
    cudaGetSymbolAddress((void**)&gfeat,g_gfeat);
    cudaGetSymbolAddress((void**)&fF,   g_featF);
    cudaGetSymbolAddress((void**)&bA,   g_bufA);
    cudaGetSymbolAddress((void**)&w1bh, g_w1bh); cudaGetSymbolAddress((void**)&w1bl, g_w1bl);
    cudaGetSymbolAddress((void**)&w1ch, g_w1ch); cudaGetSymbolAddress((void**)&w1cl, g_w1cl);
    cudaGetSymbolAddress((void**)&w2bh, g_w2bh); cudaGetSymbolAddress((void**)&w2bl, g_w2bl);
    cudaGetSymbolAddress((void**)&w2ch, g_w2ch); cudaGetSymbolAddress((void**)&w2cl, g_w2cl);
    cudaGetSymbolAddress((void**)&w3ah, g_w3ah); cudaGetSymbolAddress((void**)&w3al, g_w3al);
    cudaGetSymbolAddress((void**)&w3bh, g_w3bh); cudaGetSymbolAddress((void**)&w3bl, g_w3bl);
    cudaGetSymbolAddress((void**)&w3ch, g_w3ch); cudaGetSymbolAddress((void**)&w3cl, g_w3cl);
    cudaGetSymbolAddress((void**)&pAh,  g_pAh);  cudaGetSymbolAddress((void**)&pAl,  g_pAl);
    cudaGetSymbolAddress((void**)&pBh,  g_pBh);  cudaGetSymbolAddress((void**)&pBl,  g_pBl);
    cudaGetSymbolAddress((void**)&pCh,  g_pCh);  cudaGetSymbolAddress((void**)&pCl,  g_pCl);

    cudaFuncSetAttribute(sa1_fused_kernel, cudaFuncAttributeMaxDynamicSharedMemorySize, 97280);
    cudaFuncSetAttribute(sa2_fused_kernel, cudaFuncAttributeMaxDynamicSharedMemorySize, 144896);

    // side stream + events for graph fork (host-side objects only; created fresh,
    // never destroyed mid-capture)
    cudaStream_t s2; cudaStreamCreateWithFlags(&s2, cudaStreamNonBlocking);
    cudaEvent_t e0, eW, e1, e2;
    cudaEventCreateWithFlags(&e0, cudaEventDisableTiming);
    cudaEventCreateWithFlags(&eW, cudaEventDisableTiming);
    cudaEventCreateWithFlags(&e1, cudaEventDisableTiming);
    cudaEventCreateWithFlags(&e2, cudaEventDisableTiming);

    // fork: weight preps on s2
    cudaEventRecord(e0, 0);
    cudaStreamWaitEvent(s2, e0, 0);
    wprep_kernel<<<16, 256, 0, s2>>>(W1b, w1bh, w1bl, 64, 64);
    wprep_kernel<<<32, 256, 0, s2>>>(W1c, w1ch, w1cl, 64, 128);
    wprep_kernel<<<64, 256, 0, s2>>>(W2b, w2bh, w2bl, 128, 128);
    wprep_kernel<<<128,256, 0, s2>>>(W2c, w2ch, w2cl, 128, 256);
    wprep_pad_kernel<<<288, 256, 0, s2>>>(W3a, w3ah, w3al, 259, 256, 288);
    wprep_kernel<<<512, 256, 0, s2>>>(W3b, w3bh, w3bl, 256, 512);
    wprep_kernel<<<2048,256, 0, s2>>>(W3c, w3ch, w3cl, 512, 1024);
    cudaEventRecord(eW, s2);

    // main: curvature + FPS level 1
    curvature_kernel<<<BATCH*(NPT/128), 128>>>(pos, curv);
    fps_kernel<NPT,M1C><<<BATCH, 256>>>(pos, curv, fps1);
    gather_kernel<<<(BATCH*M1C+255)/256, 256>>>(pos, curv, fps1, pos1, curv1, NPT, M1C, BATCH*M1C);
    cudaEventRecord(e1, 0);

    // branch B on s2: FPS level 2 chain
    cudaStreamWaitEvent(s2, e1, 0);
    fps_kernel<M1C,M2C><<<BATCH, 256, 0, s2>>>(pos1, curv1, fps2);
    gather_kernel<<<(BATCH*M2C+255)/256, 256, 0, s2>>>(pos1, curv1, fps2, pos2, (float*)0, M1C, M2C, BATCH*M2C);
    group_kernel<M1C,512,4><<<dim3(M2C/4, BATCH), 128, 0, s2>>>(pos1, pos2, nidx2, cnt2, M2C, 0.16f);
    cudaEventRecord(e2, s2);

    // branch A on main: SA1
    group_kernel<NPT,128,8><<<dim3(M1C/8, BATCH), 256>>>(pos, pos1, nidx1, cnt1, M1C, 0.04f);
    cudaStreamWaitEvent(0, eW, 0);
    sa1_fused_kernel<<<152, 256, 97280>>>(pos, pos1, nidx1, cnt1,
        W1a, b1a, w1bh, w1bl, b1b, w1ch, w1cl, b1c, x1);
    gemm128_kernel<128><<<dim3(1, BATCH*M1C/128), 256>>>(x1, W2a, b2a, fF, 128, 128, 0);  // y1

    // join, SA2
    cudaStreamWaitEvent(0, e2, 0);
    sa2_fused_kernel<<<BATCH*M2C/2, 256, 144896>>>(fF, pos1, pos2, nidx2, cnt2,
        W2a, w2bh, w2bl, b2b, w2ch, w2cl, b2c, x2);

    // SA3 on tensor cores
    feats3_split_kernel<<<BATCH*M2C/2, 256>>>(x2, pos2, pAh, pAl);
    mma_gemm_kernel<<<dim3(4, 16), 256>>>(pAh, pAl, w3ah, w3al, b3a,
                                          (float*)0, pBh, pBl, 256, 288, 1);
    mma_gemm_kernel<<<dim3(8, 16), 256>>>(pBh, pBl, w3bh, w3bl, b3b,
                                          (float*)0, pCh, pCl, 512, 256, 1);
    mma_gemm_kernel<<<dim3(16, 16), 256>>>(pCh, pCl, w3ch, w3cl, b3c,
                                           bA, (__nv_bfloat16*)0, (__nv_bfloat16*)0, 1024, 512, 0);
    pool256_kernel<<<dim3(4, BATCH), 256>>>(bA, gfeat);

    // head
    head_kernel<<<BATCH, 256>>>(gfeat, Wh1, bh1, Wh2, bh2, Wh3, bh3, (float*)d_out);
}